// round 2
// baseline (speedup 1.0000x reference)
#include <cuda_runtime.h>

#define NB 4
#define NT 2048
#define ND 1024
#define NH 16
#define NHD 64
#define NM (NB*NT)   // 8192 rows

// Scratch (allocation-free rule: __device__ globals). ~100 MB total.
__device__ float g_q [NB*NH*NT*NHD];   // [B,H,T,HD]
__device__ float g_kt[NB*NH*NHD*NT];   // [B,H,HD,T]  (K projected + transposed)
__device__ float g_v [NB*NH*NT*NHD];   // [B,H,T,HD]
__device__ float g_o [NB*NH*NT*NHD];   // [B,H,T,HD] attention output

// ---------------------------------------------------------------------------
// GEMM: C[M,N] = A[M,K] @ W[N,K]^T + bias   (M=8192, N=K=1024)
// AMODE 0: A plain row-major [M,K]
// AMODE 1: A gathered from head layout [B,H,T,HD] (k index = h*64+hd)
// OMODE 0: scatter C into head layout [B,H,T,HD]
// OMODE 1: scatter C into transposed head layout [B,H,HD,T] (float4 along T)
// OMODE 2: plain row-major [M,N]
// Block tile 128x128, K-tile 16, 256 threads, 8x8 per thread.
// ---------------------------------------------------------------------------
template<int AMODE, int OMODE>
__global__ __launch_bounds__(256)
void gemm_kernel(const float* __restrict__ A, const float* __restrict__ W,
                 const float* __restrict__ bias, float* __restrict__ Cout)
{
    const int K = ND, N = ND;
    __shared__ float As[16][132];   // [k][m], padded vs bank conflicts
    __shared__ float Bs[16][132];   // [k][n]

    const int tid = threadIdx.x;
    const int tx = tid & 15;        // col group
    const int ty = tid >> 4;        // row group
    const int bm = blockIdx.y * 128;
    const int bn = blockIdx.x * 128;

    float acc[8][8];
#pragma unroll
    for (int a = 0; a < 8; a++)
#pragma unroll
        for (int b = 0; b < 8; b++) acc[a][b] = 0.f;

    for (int k0 = 0; k0 < K; k0 += 16) {
        // Load A tile (128 rows x 16 k) and W tile (128 rows x 16 k), float4
        // over k, stored transposed into smem.
#pragma unroll
        for (int l = 0; l < 2; l++) {
            int li  = l * 256 + tid;
            int row = li >> 2;          // 0..127
            int f4  = li & 3;           // 0..3 (k float4 index)
            int kk  = k0 + f4 * 4;

            float4 av;
            if (AMODE == 0) {
                av = *(const float4*)(A + (size_t)(bm + row) * K + kk);
            } else {
                int m  = bm + row;
                int b_ = m >> 11;            // /NT
                int t_ = m & (NT - 1);
                int h_ = kk >> 6;            // head (16-wide k tile never crosses a head)
                int hd = kk & 63;
                av = *(const float4*)(A + (((size_t)(b_ * NH + h_) * NT + t_) * NHD + hd));
            }
            As[f4*4+0][row] = av.x;
            As[f4*4+1][row] = av.y;
            As[f4*4+2][row] = av.z;
            As[f4*4+3][row] = av.w;

            float4 wv = *(const float4*)(W + (size_t)(bn + row) * K + kk);
            Bs[f4*4+0][row] = wv.x;
            Bs[f4*4+1][row] = wv.y;
            Bs[f4*4+2][row] = wv.z;
            Bs[f4*4+3][row] = wv.w;
        }
        __syncthreads();

#pragma unroll
        for (int kk = 0; kk < 16; kk++) {
            float av[8], bv[8];
            *(float4*)&av[0] = *(float4*)&As[kk][ty * 4];
            *(float4*)&av[4] = *(float4*)&As[kk][ty * 4 + 64];
            *(float4*)&bv[0] = *(float4*)&Bs[kk][tx * 4];
            *(float4*)&bv[4] = *(float4*)&Bs[kk][tx * 4 + 64];
#pragma unroll
            for (int a = 0; a < 8; a++)
#pragma unroll
                for (int b = 0; b < 8; b++)
                    acc[a][b] += av[a] * bv[b];
        }
        __syncthreads();
    }

    // Epilogue: bias + store
    float bb[8];
    *(float4*)&bb[0] = *(const float4*)(bias + bn + tx * 4);
    *(float4*)&bb[4] = *(const float4*)(bias + bn + tx * 4 + 64);

    if (OMODE == 1) {
        // Transposed store: for each owned column c (= h*64+hd), the 4
        // consecutive owned rows are 4 consecutive t values -> float4 along T.
#pragma unroll
        for (int ag = 0; ag < 2; ag++) {
            int m  = bm + ty * 4 + ag * 64;
            int b_ = m >> 11;
            int t_ = m & (NT - 1);
#pragma unroll
            for (int g = 0; g < 2; g++) {
#pragma unroll
                for (int j = 0; j < 4; j++) {
                    int c  = bn + tx * 4 + g * 64 + j;
                    int h_ = c >> 6, hd = c & 63;
                    float bbv = bb[g * 4 + j];
                    float4 v = make_float4(acc[ag*4+0][g*4+j] + bbv,
                                           acc[ag*4+1][g*4+j] + bbv,
                                           acc[ag*4+2][g*4+j] + bbv,
                                           acc[ag*4+3][g*4+j] + bbv);
                    *(float4*)(Cout + (((size_t)(b_ * NH + h_) * NHD + hd) * NT + t_)) = v;
                }
            }
        }
    } else {
#pragma unroll
        for (int a = 0; a < 8; a++) {
            int row = ty * 4 + (a & 3) + (a >> 2) * 64;
            int m = bm + row;
#pragma unroll
            for (int g = 0; g < 2; g++) {
                int c0 = bn + tx * 4 + g * 64;
                float4 v;
                v.x = acc[a][g*4+0] + bb[g*4+0];
                v.y = acc[a][g*4+1] + bb[g*4+1];
                v.z = acc[a][g*4+2] + bb[g*4+2];
                v.w = acc[a][g*4+3] + bb[g*4+3];
                if (OMODE == 0) {
                    int b_ = m >> 11, t_ = m & (NT - 1);
                    int h_ = c0 >> 6, hd = c0 & 63;
                    *(float4*)(Cout + (((size_t)(b_ * NH + h_) * NT + t_) * NHD + hd)) = v;
                } else {
                    *(float4*)(Cout + (size_t)m * N + c0) = v;
                }
            }
        }
    }
}

// ---------------------------------------------------------------------------
// Flash attention (fp32, online softmax). One block = 64 queries of one (b,h).
// 256 threads: thread (ty,tx) owns S/O rows 4*ty..+3, cols 4*tx..+3.
// smem rows padded to 68 floats -> float4 column accesses are conflict-free.
// ---------------------------------------------------------------------------
__global__ __launch_bounds__(256)
void attn_kernel(const float* __restrict__ qp, const float* __restrict__ ktp,
                 const float* __restrict__ vp, float* __restrict__ ao)
{
    extern __shared__ float smem[];
    float (*Qs)[68] = (float (*)[68])(smem);               // [q row][hd]
    float (*Ks)[68] = (float (*)[68])(smem + 64 * 68);     // [hd][key token]
    float (*Vs)[68] = (float (*)[68])(smem + 2 * 64 * 68); // [key token][hd]
    float (*Ps)[68] = (float (*)[68])(smem + 3 * 64 * 68); // [q row][key token]

    const int tid = threadIdx.x;
    const int tx = tid & 15, ty = tid >> 4;
    const int bh = blockIdx.y;
    const int q0 = blockIdx.x * 64;

    const float* qb = qp + ((size_t)bh * NT + q0) * NHD;
    const float* kb = ktp + (size_t)bh * NHD * NT;
    const float* vb = vp + (size_t)bh * NT * NHD;

    // Load Q tile once
#pragma unroll
    for (int l = 0; l < 4; l++) {
        int idx = l * 256 + tid;
        int r = idx >> 4, f4 = idx & 15;
        *(float4*)&Qs[r][f4 * 4] = *(const float4*)(qb + r * NHD + f4 * 4);
    }

    float o[4][4];
    float mrow[4], lrow[4];
#pragma unroll
    for (int i = 0; i < 4; i++) {
        mrow[i] = -1e30f; lrow[i] = 0.f;
#pragma unroll
        for (int j = 0; j < 4; j++) o[i][j] = 0.f;
    }

    for (int t0 = 0; t0 < NT; t0 += 64) {
        __syncthreads();   // prev iter done reading Ks/Vs/Ps; orders Qs on iter 0
#pragma unroll
        for (int l = 0; l < 4; l++) {
            int idx = l * 256 + tid;
            int r = idx >> 4, f4 = idx & 15;
            *(float4*)&Ks[r][f4 * 4] = *(const float4*)(kb + (size_t)r * NT + t0 + f4 * 4);
            *(float4*)&Vs[r][f4 * 4] = *(const float4*)(vb + (size_t)(t0 + r) * NHD + f4 * 4);
        }
        __syncthreads();

        // S = Q K^T (64x64 tile), thread computes 4x4
        float s[4][4];
#pragma unroll
        for (int i = 0; i < 4; i++)
#pragma unroll
            for (int j = 0; j < 4; j++) s[i][j] = 0.f;

#pragma unroll
        for (int k4 = 0; k4 < 16; k4++) {
            float qa[4][4];
#pragma unroll
            for (int i = 0; i < 4; i++)
                *(float4*)&qa[i][0] = *(float4*)&Qs[ty * 4 + i][k4 * 4];
#pragma unroll
            for (int kk = 0; kk < 4; kk++) {
                float4 kv = *(float4*)&Ks[k4 * 4 + kk][tx * 4];
#pragma unroll
                for (int i = 0; i < 4; i++) {
                    s[i][0] += qa[i][kk] * kv.x;
                    s[i][1] += qa[i][kk] * kv.y;
                    s[i][2] += qa[i][kk] * kv.z;
                    s[i][3] += qa[i][kk] * kv.w;
                }
            }
        }

        // Online softmax (each S row lives within one 16-lane shfl group)
#pragma unroll
        for (int i = 0; i < 4; i++) {
            float mx = -1e30f;
#pragma unroll
            for (int j = 0; j < 4; j++) {
                s[i][j] *= 0.125f;                  // 1/sqrt(64)
                mx = fmaxf(mx, s[i][j]);
            }
            mx = fmaxf(mx, __shfl_xor_sync(0xffffffffu, mx, 8, 16));
            mx = fmaxf(mx, __shfl_xor_sync(0xffffffffu, mx, 4, 16));
            mx = fmaxf(mx, __shfl_xor_sync(0xffffffffu, mx, 2, 16));
            mx = fmaxf(mx, __shfl_xor_sync(0xffffffffu, mx, 1, 16));

            float mnew = fmaxf(mrow[i], mx);
            float corr = __expf(mrow[i] - mnew);
            mrow[i] = mnew;

            float rs = 0.f;
#pragma unroll
            for (int j = 0; j < 4; j++) {
                float p = __expf(s[i][j] - mnew);
                s[i][j] = p;
                rs += p;
            }
            rs += __shfl_xor_sync(0xffffffffu, rs, 8, 16);
            rs += __shfl_xor_sync(0xffffffffu, rs, 4, 16);
            rs += __shfl_xor_sync(0xffffffffu, rs, 2, 16);
            rs += __shfl_xor_sync(0xffffffffu, rs, 1, 16);

            lrow[i] = lrow[i] * corr + rs;
#pragma unroll
            for (int j = 0; j < 4; j++) o[i][j] *= corr;

            float4 pv4 = make_float4(s[i][0], s[i][1], s[i][2], s[i][3]);
            *(float4*)&Ps[ty * 4 + i][tx * 4] = pv4;
        }
        __syncthreads();

        // O += P V  (64x64 @ 64x64)
#pragma unroll
        for (int j4 = 0; j4 < 16; j4++) {
            float pa[4][4];
#pragma unroll
            for (int i = 0; i < 4; i++)
                *(float4*)&pa[i][0] = *(float4*)&Ps[ty * 4 + i][j4 * 4];
#pragma unroll
            for (int jj = 0; jj < 4; jj++) {
                float4 vv = *(float4*)&Vs[j4 * 4 + jj][tx * 4];
#pragma unroll
                for (int i = 0; i < 4; i++) {
                    o[i][0] += pa[i][jj] * vv.x;
                    o[i][1] += pa[i][jj] * vv.y;
                    o[i][2] += pa[i][jj] * vv.z;
                    o[i][3] += pa[i][jj] * vv.w;
                }
            }
        }
    }

    // Normalize and store [B,H,T,HD]
    float* ob = ao + ((size_t)bh * NT + q0) * NHD;
#pragma unroll
    for (int i = 0; i < 4; i++) {
        float inv = 1.f / lrow[i];
        float4 v = make_float4(o[i][0] * inv, o[i][1] * inv, o[i][2] * inv, o[i][3] * inv);
        *(float4*)(ob + (ty * 4 + i) * NHD + tx * 4) = v;
    }
}

// ---------------------------------------------------------------------------
extern "C" void kernel_launch(void* const* d_in, const int* in_sizes, int n_in,
                              void* d_out, int out_size)
{
    const float* q  = (const float*)d_in[0];
    const float* k  = (const float*)d_in[1];
    const float* v  = (const float*)d_in[2];
    const float* Wq = (const float*)d_in[3];
    const float* bq = (const float*)d_in[4];
    const float* Wk = (const float*)d_in[5];
    const float* bk = (const float*)d_in[6];
    const float* Wv = (const float*)d_in[7];
    const float* bv = (const float*)d_in[8];
    const float* Wo = (const float*)d_in[9];
    const float* bo = (const float*)d_in[10];
    float* out = (float*)d_out;

    float *pq, *pkt, *pv, *po;
    cudaGetSymbolAddress((void**)&pq,  g_q);
    cudaGetSymbolAddress((void**)&pkt, g_kt);
    cudaGetSymbolAddress((void**)&pv,  g_v);
    cudaGetSymbolAddress((void**)&po,  g_o);

    dim3 gg(ND / 128, NM / 128);   // (8, 64)

    gemm_kernel<0, 0><<<gg, 256>>>(q, Wq, bq, pq);
    gemm_kernel<0, 1><<<gg, 256>>>(k, Wk, bk, pkt);   // K proj + transpose fused
    gemm_kernel<0, 0><<<gg, 256>>>(v, Wv, bv, pv);

    int smem_bytes = 4 * 64 * 68 * (int)sizeof(float);   // 69,632 B
    cudaFuncSetAttribute(attn_kernel, cudaFuncAttributeMaxDynamicSharedMemorySize, smem_bytes);
    attn_kernel<<<dim3(NT / 64, NB * NH), 256, smem_bytes>>>(pq, pkt, pv, po);

    gemm_kernel<1, 2><<<gg, 256>>>(po, Wo, bo, out);
}

// round 3
// speedup vs baseline: 1.3325x; 1.3325x over previous
#include <cuda_runtime.h>
#include <cstdint>

#define NB 4
#define NT 2048
#define ND 1024
#define NH 16
#define NHD 64
#define NM (NB*NT)   // 8192 rows

// Scratch (allocation-free rule: __device__ globals). ~100 MB total.
__device__ float g_q [NB*NH*NT*NHD];   // [B,H,T,HD]
__device__ float g_kt[NB*NH*NHD*NT];   // [B,H,HD,T]  (K projected + transposed)
__device__ float g_v [NB*NH*NT*NHD];   // [B,H,T,HD]
__device__ float g_o [NB*NH*NT*NHD];   // [B,H,T,HD] attention output

__device__ __forceinline__ unsigned f2tf(float f) {
    unsigned u;
    asm("cvt.rna.tf32.f32 %0, %1;" : "=r"(u) : "f"(f));
    return u;
}

__device__ __forceinline__ void mma_tf32(float c[4], const unsigned a[4], const unsigned b[2]) {
    asm volatile(
        "mma.sync.aligned.m16n8k8.row.col.f32.tf32.tf32.f32 "
        "{%0,%1,%2,%3}, {%4,%5,%6,%7}, {%8,%9}, {%0,%1,%2,%3};"
        : "+f"(c[0]), "+f"(c[1]), "+f"(c[2]), "+f"(c[3])
        : "r"(a[0]), "r"(a[1]), "r"(a[2]), "r"(a[3]), "r"(b[0]), "r"(b[1]));
}

// ---------------------------------------------------------------------------
// Tensor-core tf32 GEMM: C[M,N] = A[M,K] @ W[N,K]^T + bias  (M=8192, N=K=1024)
// AMODE 0: A plain row-major [M,K]
// AMODE 1: A gathered from head layout [B,H,T,HD] (k index = h*64+hd)
// OMODE 0: scatter C into head layout [B,H,T,HD]
// OMODE 1: scatter C into transposed head layout [B,H,HD,T]
// OMODE 2: plain row-major [M,N]
//
// Block 128x128, ktile 32, 256 threads (8 warps, warp tile 64x32), smem holds
// A/W tiles in mma.sync fragment order ([lane][reg]) so fragment loads are
// single LDS.128 / LDS.64. Double buffered; one __syncthreads per stage.
//
// Fragment maps (PTX m16n8k8 tf32):
//  A(16x8): reg = (k%8>=4 ? 2:0) + (m%16>=8 ? 1:0), lane = (m%8)*4 + k%4
//  B(8x8) : reg = (k%8)/4,                           lane = (n%8)*4 + k%4
//  C(16x8): c0=(r, 2c) c1=(r, 2c+1) c2=(r+8, 2c) c3=(r+8, 2c+1); r=lane/4, c=lane%4
// smem tiles: A tile 512B at ((mt*4+kt)<<7), addr = lane*4+reg (floats)
//             W tile 256B at ((nt*4+kt)<<6), addr = lane*2+reg (floats)
// ---------------------------------------------------------------------------
template<int AMODE, int OMODE>
__global__ __launch_bounds__(256)
void gemm_tc(const float* __restrict__ A, const float* __restrict__ W,
             const float* __restrict__ bias, float* __restrict__ Cout)
{
    extern __shared__ unsigned sh[];
    unsigned* As = sh;           // 2 bufs x 4096 u32 (16 KB each)
    unsigned* Ws = sh + 8192;    // 2 bufs x 4096 u32

    const int tid  = threadIdx.x;
    const int lane = tid & 31;
    const int warp = tid >> 5;
    const int wm   = warp & 1;      // warp m group (0..1) -> rows wm*64
    const int wn   = warp >> 1;     // warp n group (0..3) -> cols wn*32
    const int bm   = blockIdx.y * 128;
    const int bn   = blockIdx.x * 128;

    float acc[4][4][4];
#pragma unroll
    for (int mi = 0; mi < 4; mi++)
#pragma unroll
        for (int nj = 0; nj < 4; nj++)
#pragma unroll
            for (int r = 0; r < 4; r++) acc[mi][nj][r] = 0.f;

    float4 ar[4], wr[4];

    auto ldg = [&](int s) {
#pragma unroll
        for (int l = 0; l < 4; l++) {
            int idx = l * 256 + tid;
            int row = idx >> 3;          // 0..127
            int kq  = idx & 7;           // float4 index within ktile
            int kg  = s * 32 + kq * 4;   // global k
            if (AMODE == 0) {
                ar[l] = *(const float4*)(A + (size_t)(bm + row) * ND + kg);
            } else {
                int m  = bm + row;
                int b_ = m >> 11, t_ = m & (NT - 1);
                int h_ = kg >> 6, hd = kg & 63;
                ar[l] = *(const float4*)(A + (((size_t)(b_ * NH + h_) * NT + t_) * NHD + hd));
            }
            wr[l] = *(const float4*)(W + (size_t)(bn + row) * ND + kg);
        }
    };

    auto sts = [&](int buf) {
        unsigned* ab = As + buf * 4096;
        unsigned* wb = Ws + buf * 4096;
#pragma unroll
        for (int l = 0; l < 4; l++) {
            int idx = l * 256 + tid;
            int row = idx >> 3;
            int kq  = idx & 7;
            // A: tile (mt = row/16, kt = kq/2)
            {
                unsigned* p = ab + (((row >> 4) * 4 + (kq >> 1)) << 7);
                int reg = ((kq & 1) << 1) + ((row >> 3) & 1);
                int lb  = (row & 7) * 4;
                p[(lb + 0) * 4 + reg] = f2tf(ar[l].x);
                p[(lb + 1) * 4 + reg] = f2tf(ar[l].y);
                p[(lb + 2) * 4 + reg] = f2tf(ar[l].z);
                p[(lb + 3) * 4 + reg] = f2tf(ar[l].w);
            }
            // W: tile (nt = row/8, kt = kq/2)
            {
                unsigned* p = wb + (((row >> 3) * 4 + (kq >> 1)) << 6);
                int reg = (kq & 1);
                int lb  = (row & 7) * 4;
                p[(lb + 0) * 2 + reg] = f2tf(wr[l].x);
                p[(lb + 1) * 2 + reg] = f2tf(wr[l].y);
                p[(lb + 2) * 2 + reg] = f2tf(wr[l].z);
                p[(lb + 3) * 2 + reg] = f2tf(wr[l].w);
            }
        }
    };

    auto compute = [&](int buf) {
        const unsigned* ab = As + buf * 4096;
        const unsigned* wb = Ws + buf * 4096;
#pragma unroll
        for (int kt = 0; kt < 4; kt++) {
            unsigned af[4][4];
#pragma unroll
            for (int mi = 0; mi < 4; mi++) {
                uint4 t = *(const uint4*)(ab + ((((wm * 4 + mi) * 4 + kt)) << 7) + (lane << 2));
                af[mi][0] = t.x; af[mi][1] = t.y; af[mi][2] = t.z; af[mi][3] = t.w;
            }
            unsigned bf[4][2];
#pragma unroll
            for (int nj = 0; nj < 4; nj++) {
                uint2 t = *(const uint2*)(wb + ((((wn * 4 + nj) * 4 + kt)) << 6) + (lane << 1));
                bf[nj][0] = t.x; bf[nj][1] = t.y;
            }
#pragma unroll
            for (int mi = 0; mi < 4; mi++)
#pragma unroll
                for (int nj = 0; nj < 4; nj++)
                    mma_tf32(acc[mi][nj], af[mi], bf[nj]);
        }
    };

    // Pipeline: prologue stage 0, then one sync per stage.
    ldg(0);
    sts(0);
    __syncthreads();
    for (int s = 0; s < 32; s++) {
        int buf = s & 1;
        if (s < 31) ldg(s + 1);
        compute(buf);
        if (s < 31) sts(buf ^ 1);
        __syncthreads();
    }

    // Epilogue
#pragma unroll
    for (int nj = 0; nj < 4; nj++) {
        int col = bn + (wn * 4 + nj) * 8 + (lane & 3) * 2;
        float b0 = bias[col], b1 = bias[col + 1];
#pragma unroll
        for (int mi = 0; mi < 4; mi++) {
            int row = bm + (wm * 4 + mi) * 16 + (lane >> 2);
            float v00 = acc[mi][nj][0] + b0, v01 = acc[mi][nj][1] + b1;
            float v10 = acc[mi][nj][2] + b0, v11 = acc[mi][nj][3] + b1;
            if (OMODE == 2) {
                *(float2*)(Cout + (size_t)row * ND + col)       = make_float2(v00, v01);
                *(float2*)(Cout + (size_t)(row + 8) * ND + col) = make_float2(v10, v11);
            } else if (OMODE == 0) {
                int b_ = row >> 11, t_ = row & (NT - 1);
                int h_ = col >> 6, hd = col & 63;
                float* p = Cout + (((size_t)(b_ * NH + h_) * NT + t_) * NHD + hd);
                *(float2*)p             = make_float2(v00, v01);   // (t_,   hd)
                *(float2*)(p + 8 * NHD) = make_float2(v10, v11);   // (t_+8, hd) same b (128|2048)
            } else { // OMODE 1: [B,H,HD,T]
                int b_ = row >> 11, t_ = row & (NT - 1);
                int h_ = col >> 6, hd = col & 63;   // col even -> col,col+1 same head
                float* p = Cout + (((size_t)(b_ * NH + h_) * NHD + hd) * NT + t_);
                p[0]          = v00;
                p[NT]         = v01;   // hd+1
                p[8]          = v10;   // t_+8
                p[NT + 8]     = v11;
            }
        }
    }
}

// ---------------------------------------------------------------------------
// Flash attention (fp32, online softmax). One block = 64 queries of one (b,h).
// 256 threads: thread (ty,tx) owns S/O rows 4*ty..+3, cols 4*tx..+3.
// smem rows padded to 68 floats -> float4 column accesses are conflict-free.
// ---------------------------------------------------------------------------
__global__ __launch_bounds__(256)
void attn_kernel(const float* __restrict__ qp, const float* __restrict__ ktp,
                 const float* __restrict__ vp, float* __restrict__ ao)
{
    extern __shared__ float smem[];
    float (*Qs)[68] = (float (*)[68])(smem);               // [q row][hd]
    float (*Ks)[68] = (float (*)[68])(smem + 64 * 68);     // [hd][key token]
    float (*Vs)[68] = (float (*)[68])(smem + 2 * 64 * 68); // [key token][hd]
    float (*Ps)[68] = (float (*)[68])(smem + 3 * 64 * 68); // [q row][key token]

    const int tid = threadIdx.x;
    const int tx = tid & 15, ty = tid >> 4;
    const int bh = blockIdx.y;
    const int q0 = blockIdx.x * 64;

    const float* qb = qp + ((size_t)bh * NT + q0) * NHD;
    const float* kb = ktp + (size_t)bh * NHD * NT;
    const float* vb = vp + (size_t)bh * NT * NHD;

#pragma unroll
    for (int l = 0; l < 4; l++) {
        int idx = l * 256 + tid;
        int r = idx >> 4, f4 = idx & 15;
        *(float4*)&Qs[r][f4 * 4] = *(const float4*)(qb + r * NHD + f4 * 4);
    }

    float o[4][4];
    float mrow[4], lrow[4];
#pragma unroll
    for (int i = 0; i < 4; i++) {
        mrow[i] = -1e30f; lrow[i] = 0.f;
#pragma unroll
        for (int j = 0; j < 4; j++) o[i][j] = 0.f;
    }

    for (int t0 = 0; t0 < NT; t0 += 64) {
        __syncthreads();   // prev iter done reading Ks/Vs/Ps; orders Qs on iter 0
#pragma unroll
        for (int l = 0; l < 4; l++) {
            int idx = l * 256 + tid;
            int r = idx >> 4, f4 = idx & 15;
            *(float4*)&Ks[r][f4 * 4] = *(const float4*)(kb + (size_t)r * NT + t0 + f4 * 4);
            *(float4*)&Vs[r][f4 * 4] = *(const float4*)(vb + (size_t)(t0 + r) * NHD + f4 * 4);
        }
        __syncthreads();

        float s[4][4];
#pragma unroll
        for (int i = 0; i < 4; i++)
#pragma unroll
            for (int j = 0; j < 4; j++) s[i][j] = 0.f;

#pragma unroll
        for (int k4 = 0; k4 < 16; k4++) {
            float qa[4][4];
#pragma unroll
            for (int i = 0; i < 4; i++)
                *(float4*)&qa[i][0] = *(float4*)&Qs[ty * 4 + i][k4 * 4];
#pragma unroll
            for (int kk = 0; kk < 4; kk++) {
                float4 kv = *(float4*)&Ks[k4 * 4 + kk][tx * 4];
#pragma unroll
                for (int i = 0; i < 4; i++) {
                    s[i][0] += qa[i][kk] * kv.x;
                    s[i][1] += qa[i][kk] * kv.y;
                    s[i][2] += qa[i][kk] * kv.z;
                    s[i][3] += qa[i][kk] * kv.w;
                }
            }
        }

#pragma unroll
        for (int i = 0; i < 4; i++) {
            float mx = -1e30f;
#pragma unroll
            for (int j = 0; j < 4; j++) {
                s[i][j] *= 0.125f;                  // 1/sqrt(64)
                mx = fmaxf(mx, s[i][j]);
            }
            mx = fmaxf(mx, __shfl_xor_sync(0xffffffffu, mx, 8, 16));
            mx = fmaxf(mx, __shfl_xor_sync(0xffffffffu, mx, 4, 16));
            mx = fmaxf(mx, __shfl_xor_sync(0xffffffffu, mx, 2, 16));
            mx = fmaxf(mx, __shfl_xor_sync(0xffffffffu, mx, 1, 16));

            float mnew = fmaxf(mrow[i], mx);
            float corr = __expf(mrow[i] - mnew);
            mrow[i] = mnew;

            float rs = 0.f;
#pragma unroll
            for (int j = 0; j < 4; j++) {
                float p = __expf(s[i][j] - mnew);
                s[i][j] = p;
                rs += p;
            }
            rs += __shfl_xor_sync(0xffffffffu, rs, 8, 16);
            rs += __shfl_xor_sync(0xffffffffu, rs, 4, 16);
            rs += __shfl_xor_sync(0xffffffffu, rs, 2, 16);
            rs += __shfl_xor_sync(0xffffffffu, rs, 1, 16);

            lrow[i] = lrow[i] * corr + rs;
#pragma unroll
            for (int j = 0; j < 4; j++) o[i][j] *= corr;

            *(float4*)&Ps[ty * 4 + i][tx * 4] = make_float4(s[i][0], s[i][1], s[i][2], s[i][3]);
        }
        __syncthreads();

#pragma unroll
        for (int j4 = 0; j4 < 16; j4++) {
            float pa[4][4];
#pragma unroll
            for (int i = 0; i < 4; i++)
                *(float4*)&pa[i][0] = *(float4*)&Ps[ty * 4 + i][j4 * 4];
#pragma unroll
            for (int jj = 0; jj < 4; jj++) {
                float4 vv = *(float4*)&Vs[j4 * 4 + jj][tx * 4];
#pragma unroll
                for (int i = 0; i < 4; i++) {
                    o[i][0] += pa[i][jj] * vv.x;
                    o[i][1] += pa[i][jj] * vv.y;
                    o[i][2] += pa[i][jj] * vv.z;
                    o[i][3] += pa[i][jj] * vv.w;
                }
            }
        }
    }

    float* ob = ao + ((size_t)bh * NT + q0) * NHD;
#pragma unroll
    for (int i = 0; i < 4; i++) {
        float inv = 1.f / lrow[i];
        *(float4*)(ob + (ty * 4 + i) * NHD + tx * 4) =
            make_float4(o[i][0] * inv, o[i][1] * inv, o[i][2] * inv, o[i][3] * inv);
    }
}

// ---------------------------------------------------------------------------
extern "C" void kernel_launch(void* const* d_in, const int* in_sizes, int n_in,
                              void* d_out, int out_size)
{
    const float* q  = (const float*)d_in[0];
    const float* k  = (const float*)d_in[1];
    const float* v  = (const float*)d_in[2];
    const float* Wq = (const float*)d_in[3];
    const float* bq = (const float*)d_in[4];
    const float* Wk = (const float*)d_in[5];
    const float* bk = (const float*)d_in[6];
    const float* Wv = (const float*)d_in[7];
    const float* bv = (const float*)d_in[8];
    const float* Wo = (const float*)d_in[9];
    const float* bo = (const float*)d_in[10];
    float* out = (float*)d_out;

    float *pq, *pkt, *pv, *po;
    cudaGetSymbolAddress((void**)&pq,  g_q);
    cudaGetSymbolAddress((void**)&pkt, g_kt);
    cudaGetSymbolAddress((void**)&pv,  g_v);
    cudaGetSymbolAddress((void**)&po,  g_o);

    const int gemm_smem = 65536;   // 2 x (16KB A + 16KB W)
    cudaFuncSetAttribute(gemm_tc<0,0>, cudaFuncAttributeMaxDynamicSharedMemorySize, gemm_smem);
    cudaFuncSetAttribute(gemm_tc<0,1>, cudaFuncAttributeMaxDynamicSharedMemorySize, gemm_smem);
    cudaFuncSetAttribute(gemm_tc<1,2>, cudaFuncAttributeMaxDynamicSharedMemorySize, gemm_smem);

    dim3 gg(ND / 128, NM / 128);   // (8, 64)

    gemm_tc<0, 0><<<gg, 256, gemm_smem>>>(q, Wq, bq, pq);
    gemm_tc<0, 1><<<gg, 256, gemm_smem>>>(k, Wk, bk, pkt);   // K proj + transpose fused
    gemm_tc<0, 0><<<gg, 256, gemm_smem>>>(v, Wv, bv, pv);

    int attn_smem = 4 * 64 * 68 * (int)sizeof(float);   // 69,632 B
    cudaFuncSetAttribute(attn_kernel, cudaFuncAttributeMaxDynamicSharedMemorySize, attn_smem);
    attn_kernel<<<dim3(NT / 64, NB * NH), 256, attn_smem>>>(pq, pkt, pv, po);

    gemm_tc<1, 2><<<gg, 256, gemm_smem>>>(po, Wo, bo, out);
}

// round 5
// speedup vs baseline: 1.5728x; 1.1803x over previous
#include <cuda_runtime.h>
#include <cstdint>

#define NB 4
#define NT 2048
#define ND 1024
#define NH 16
#define NHD 64
#define NM (NB*NT)   // 8192 rows

// Scratch (allocation-free rule: __device__ globals).
__device__ float g_q [NB*NH*NT*NHD];   // [B,H,T,HD]
__device__ float g_kt[NB*NH*NHD*NT];   // [B,H,HD,T]  (K projected + transposed)
__device__ float g_v [NB*NH*NT*NHD];   // [B,H,T,HD]
__device__ float g_o [NB*NH*NT*NHD];   // [B,H,T,HD] attention output

__device__ __forceinline__ unsigned f2tf(float f) {
    unsigned u;
    asm("cvt.rna.tf32.f32 %0, %1;" : "=r"(u) : "f"(f));
    return u;
}
__device__ __forceinline__ float tf32r(float f) { return __uint_as_float(f2tf(f)); }

__device__ __forceinline__ void mma_tf32(float c[4], const unsigned a[4], const unsigned b[2]) {
    asm volatile(
        "mma.sync.aligned.m16n8k8.row.col.f32.tf32.tf32.f32 "
        "{%0,%1,%2,%3}, {%4,%5,%6,%7}, {%8,%9}, {%0,%1,%2,%3};"
        : "+f"(c[0]), "+f"(c[1]), "+f"(c[2]), "+f"(c[3])
        : "r"(a[0]), "r"(a[1]), "r"(a[2]), "r"(a[3]), "r"(b[0]), "r"(b[1]));
}
__device__ __forceinline__ void mma_f(float c[4], const float a[4], const float b0, const float b1) {
    asm volatile(
        "mma.sync.aligned.m16n8k8.row.col.f32.tf32.tf32.f32 "
        "{%0,%1,%2,%3}, {%4,%5,%6,%7}, {%8,%9}, {%0,%1,%2,%3};"
        : "+f"(c[0]), "+f"(c[1]), "+f"(c[2]), "+f"(c[3])
        : "r"(__float_as_uint(a[0])), "r"(__float_as_uint(a[1])),
          "r"(__float_as_uint(a[2])), "r"(__float_as_uint(a[3])),
          "r"(__float_as_uint(b0)),   "r"(__float_as_uint(b1)));
}

// ---------------------------------------------------------------------------
// Tensor-core tf32 GEMM (verbatim from passing R3): C = A @ W^T + bias.
// ---------------------------------------------------------------------------
template<int AMODE, int OMODE>
__global__ __launch_bounds__(256)
void gemm_tc(const float* __restrict__ A, const float* __restrict__ W,
             const float* __restrict__ bias, float* __restrict__ Cout)
{
    extern __shared__ unsigned sh[];
    unsigned* As = sh;           // 2 bufs x 4096 u32
    unsigned* Ws = sh + 8192;

    const int tid  = threadIdx.x;
    const int lane = tid & 31;
    const int warp = tid >> 5;
    const int wm   = warp & 1;
    const int wn   = warp >> 1;
    const int bm   = blockIdx.y * 128;
    const int bn   = blockIdx.x * 128;

    float acc[4][4][4];
#pragma unroll
    for (int mi = 0; mi < 4; mi++)
#pragma unroll
        for (int nj = 0; nj < 4; nj++)
#pragma unroll
            for (int r = 0; r < 4; r++) acc[mi][nj][r] = 0.f;

    float4 ar[4], wr[4];

    auto ldg = [&](int s) {
#pragma unroll
        for (int l = 0; l < 4; l++) {
            int idx = l * 256 + tid;
            int row = idx >> 3;
            int kq  = idx & 7;
            int kg  = s * 32 + kq * 4;
            if (AMODE == 0) {
                ar[l] = *(const float4*)(A + (size_t)(bm + row) * ND + kg);
            } else {
                int m  = bm + row;
                int b_ = m >> 11, t_ = m & (NT - 1);
                int h_ = kg >> 6, hd = kg & 63;
                ar[l] = *(const float4*)(A + (((size_t)(b_ * NH + h_) * NT + t_) * NHD + hd));
            }
            wr[l] = *(const float4*)(W + (size_t)(bn + row) * ND + kg);
        }
    };

    auto sts = [&](int buf) {
        unsigned* ab = As + buf * 4096;
        unsigned* wb = Ws + buf * 4096;
#pragma unroll
        for (int l = 0; l < 4; l++) {
            int idx = l * 256 + tid;
            int row = idx >> 3;
            int kq  = idx & 7;
            {
                unsigned* p = ab + (((row >> 4) * 4 + (kq >> 1)) << 7);
                int reg = ((kq & 1) << 1) + ((row >> 3) & 1);
                int lb  = (row & 7) * 4;
                p[(lb + 0) * 4 + reg] = f2tf(ar[l].x);
                p[(lb + 1) * 4 + reg] = f2tf(ar[l].y);
                p[(lb + 2) * 4 + reg] = f2tf(ar[l].z);
                p[(lb + 3) * 4 + reg] = f2tf(ar[l].w);
            }
            {
                unsigned* p = wb + (((row >> 3) * 4 + (kq >> 1)) << 6);
                int reg = (kq & 1);
                int lb  = (row & 7) * 4;
                p[(lb + 0) * 2 + reg] = f2tf(wr[l].x);
                p[(lb + 1) * 2 + reg] = f2tf(wr[l].y);
                p[(lb + 2) * 2 + reg] = f2tf(wr[l].z);
                p[(lb + 3) * 2 + reg] = f2tf(wr[l].w);
            }
        }
    };

    auto compute = [&](int buf) {
        const unsigned* ab = As + buf * 4096;
        const unsigned* wb = Ws + buf * 4096;
#pragma unroll
        for (int kt = 0; kt < 4; kt++) {
            unsigned af[4][4];
#pragma unroll
            for (int mi = 0; mi < 4; mi++) {
                uint4 t = *(const uint4*)(ab + ((((wm * 4 + mi) * 4 + kt)) << 7) + (lane << 2));
                af[mi][0] = t.x; af[mi][1] = t.y; af[mi][2] = t.z; af[mi][3] = t.w;
            }
            unsigned bf[4][2];
#pragma unroll
            for (int nj = 0; nj < 4; nj++) {
                uint2 t = *(const uint2*)(wb + ((((wn * 4 + nj) * 4 + kt)) << 6) + (lane << 1));
                bf[nj][0] = t.x; bf[nj][1] = t.y;
            }
#pragma unroll
            for (int mi = 0; mi < 4; mi++)
#pragma unroll
                for (int nj = 0; nj < 4; nj++)
                    mma_tf32(acc[mi][nj], af[mi], bf[nj]);
        }
    };

    ldg(0);
    sts(0);
    __syncthreads();
    for (int s = 0; s < 32; s++) {
        int buf = s & 1;
        if (s < 31) ldg(s + 1);
        compute(buf);
        if (s < 31) sts(buf ^ 1);
        __syncthreads();
    }

#pragma unroll
    for (int nj = 0; nj < 4; nj++) {
        int col = bn + (wn * 4 + nj) * 8 + (lane & 3) * 2;
        float b0 = bias[col], b1 = bias[col + 1];
#pragma unroll
        for (int mi = 0; mi < 4; mi++) {
            int row = bm + (wm * 4 + mi) * 16 + (lane >> 2);
            float v00 = acc[mi][nj][0] + b0, v01 = acc[mi][nj][1] + b1;
            float v10 = acc[mi][nj][2] + b0, v11 = acc[mi][nj][3] + b1;
            if (OMODE == 2) {
                *(float2*)(Cout + (size_t)row * ND + col)       = make_float2(v00, v01);
                *(float2*)(Cout + (size_t)(row + 8) * ND + col) = make_float2(v10, v11);
            } else if (OMODE == 0) {
                int b_ = row >> 11, t_ = row & (NT - 1);
                int h_ = col >> 6, hd = col & 63;
                float* p = Cout + (((size_t)(b_ * NH + h_) * NT + t_) * NHD + hd);
                *(float2*)p             = make_float2(v00, v01);
                *(float2*)(p + 8 * NHD) = make_float2(v10, v11);
            } else { // OMODE 1: [B,H,HD,T]
                int b_ = row >> 11, t_ = row & (NT - 1);
                int h_ = col >> 6, hd = col & 63;
                float* p = Cout + (((size_t)(b_ * NH + h_) * NHD + hd) * NT + t_);
                p[0]      = v00;
                p[NT]     = v01;
                p[8]      = v10;
                p[NT + 8] = v11;
            }
        }
    }
}

// ---------------------------------------------------------------------------
// Flash attention on tf32 mma.sync with hi/lo compensation.
// 128 threads = 4 warps; CTA = 64 queries of one (b,h); 32 key-tiles of 64.
// Warp w owns S/O rows w*16..w*16+15 (m16n8k8 tiles, 8 n-tiles of 8).
// S = qh*kh + qh*kl + ql*kh (fp32-accurate); PV = p*vh + p*vl; p single tf32
// with row-sum l computed from the rounded p (consistent normalization).
// smem: Qh Ql Kh Kl Vh Vl, each [64][68] floats (104448 B total).
//   Q rows=q, cols=hd;  K rows=hd, cols=key (from g_kt);  V rows=key, cols=hd.
// ---------------------------------------------------------------------------
__global__ __launch_bounds__(128)
void attn_mma(const float* __restrict__ qp, const float* __restrict__ ktp,
              const float* __restrict__ vp, float* __restrict__ ao)
{
    extern __shared__ float smf[];
    float (*Qh)[68] = (float (*)[68])(smf);
    float (*Ql)[68] = (float (*)[68])(smf + 1 * 64 * 68);
    float (*Kh)[68] = (float (*)[68])(smf + 2 * 64 * 68);
    float (*Kl)[68] = (float (*)[68])(smf + 3 * 64 * 68);
    float (*Vh)[68] = (float (*)[68])(smf + 4 * 64 * 68);
    float (*Vl)[68] = (float (*)[68])(smf + 5 * 64 * 68);

    const int tid  = threadIdx.x;
    const int lane = tid & 31;
    const int warp = tid >> 5;
    const int wr   = warp * 16;          // warp's row base in the 64-q tile
    const int r    = lane >> 2;          // 0..7
    const int g    = lane & 3;           // 0..3
    const int bh   = blockIdx.y;
    const int q0   = blockIdx.x * 64;

    const float* qb = qp  + ((size_t)bh * NT + q0) * NHD;
    const float* kb = ktp + (size_t)bh * NHD * NT;
    const float* vb = vp  + (size_t)bh * NT * NHD;

    // Stage Q (hi/lo) once: 64 rows x 16 float4.
#pragma unroll
    for (int i = 0; i < 8; i++) {
        int idx = i * 128 + tid;
        int row = idx >> 4, f4 = idx & 15;
        float4 x = *(const float4*)(qb + row * NHD + f4 * 4);
        float4 h = make_float4(tf32r(x.x), tf32r(x.y), tf32r(x.z), tf32r(x.w));
        float4 l = make_float4(tf32r(x.x - h.x), tf32r(x.y - h.y),
                               tf32r(x.z - h.z), tf32r(x.w - h.w));
        *(float4*)&Qh[row][f4 * 4] = h;
        *(float4*)&Ql[row][f4 * 4] = l;
    }

    float o[8][4];
#pragma unroll
    for (int nt = 0; nt < 8; nt++)
#pragma unroll
        for (int c = 0; c < 4; c++) o[nt][c] = 0.f;
    float m0 = -1e30f, m1 = -1e30f, l0 = 0.f, l1 = 0.f;

    for (int t0 = 0; t0 < NT; t0 += 64) {
        __syncthreads();   // prev compute done before restaging (covers Q on iter 0)
        // Stage K (rows=hd, cols=key) and V (rows=key, cols=hd), hi/lo.
#pragma unroll
        for (int i = 0; i < 8; i++) {
            int idx = i * 128 + tid;
            int row = idx >> 4, f4 = idx & 15;
            {
                float4 x = *(const float4*)(kb + (size_t)row * NT + t0 + f4 * 4);
                float4 h = make_float4(tf32r(x.x), tf32r(x.y), tf32r(x.z), tf32r(x.w));
                float4 l = make_float4(tf32r(x.x - h.x), tf32r(x.y - h.y),
                                       tf32r(x.z - h.z), tf32r(x.w - h.w));
                *(float4*)&Kh[row][f4 * 4] = h;
                *(float4*)&Kl[row][f4 * 4] = l;
            }
            {
                float4 x = *(const float4*)(vb + (size_t)(t0 + row) * NHD + f4 * 4);
                float4 h = make_float4(tf32r(x.x), tf32r(x.y), tf32r(x.z), tf32r(x.w));
                float4 l = make_float4(tf32r(x.x - h.x), tf32r(x.y - h.y),
                                       tf32r(x.z - h.z), tf32r(x.w - h.w));
                *(float4*)&Vh[row][f4 * 4] = h;
                *(float4*)&Vl[row][f4 * 4] = l;
            }
        }
        __syncthreads();

        // ---- S = Q K^T : 8 n-tiles x 8 k-tiles, 3 compensation chains ----
        float s[8][4];
#pragma unroll
        for (int nt = 0; nt < 8; nt++)
#pragma unroll
            for (int c = 0; c < 4; c++) s[nt][c] = 0.f;

#pragma unroll
        for (int kt = 0; kt < 8; kt++) {
            float ah[4], al[4];
            ah[0] = Qh[wr + r][kt * 8 + g];     al[0] = Ql[wr + r][kt * 8 + g];
            ah[1] = Qh[wr + r + 8][kt * 8 + g]; al[1] = Ql[wr + r + 8][kt * 8 + g];
            ah[2] = Qh[wr + r][kt * 8 + g + 4]; al[2] = Ql[wr + r][kt * 8 + g + 4];
            ah[3] = Qh[wr + r + 8][kt * 8 + g + 4]; al[3] = Ql[wr + r + 8][kt * 8 + g + 4];
            float bhf[8][2], blf[8][2];
#pragma unroll
            for (int nt = 0; nt < 8; nt++) {
                bhf[nt][0] = Kh[kt * 8 + g][nt * 8 + r];
                bhf[nt][1] = Kh[kt * 8 + g + 4][nt * 8 + r];
                blf[nt][0] = Kl[kt * 8 + g][nt * 8 + r];
                blf[nt][1] = Kl[kt * 8 + g + 4][nt * 8 + r];
            }
#pragma unroll
            for (int nt = 0; nt < 8; nt++) mma_f(s[nt], ah, bhf[nt][0], bhf[nt][1]);
#pragma unroll
            for (int nt = 0; nt < 8; nt++) mma_f(s[nt], ah, blf[nt][0], blf[nt][1]);
#pragma unroll
            for (int nt = 0; nt < 8; nt++) mma_f(s[nt], al, bhf[nt][0], bhf[nt][1]);
        }

        // ---- online softmax on fragments (rows r and r+8, quad-wide) ----
        float mx0 = -1e30f, mx1 = -1e30f;
#pragma unroll
        for (int nt = 0; nt < 8; nt++) {
            s[nt][0] *= 0.125f; s[nt][1] *= 0.125f;
            s[nt][2] *= 0.125f; s[nt][3] *= 0.125f;
            mx0 = fmaxf(mx0, fmaxf(s[nt][0], s[nt][1]));
            mx1 = fmaxf(mx1, fmaxf(s[nt][2], s[nt][3]));
        }
        mx0 = fmaxf(mx0, __shfl_xor_sync(0xffffffffu, mx0, 1));
        mx0 = fmaxf(mx0, __shfl_xor_sync(0xffffffffu, mx0, 2));
        mx1 = fmaxf(mx1, __shfl_xor_sync(0xffffffffu, mx1, 1));
        mx1 = fmaxf(mx1, __shfl_xor_sync(0xffffffffu, mx1, 2));

        float mn0 = fmaxf(m0, mx0), mn1 = fmaxf(m1, mx1);
        float c0 = __expf(m0 - mn0), c1 = __expf(m1 - mn1);
        m0 = mn0; m1 = mn1;

        float rs0 = 0.f, rs1 = 0.f;
#pragma unroll
        for (int nt = 0; nt < 8; nt++) {
            float p;
            p = tf32r(__expf(s[nt][0] - mn0)); s[nt][0] = p; rs0 += p;
            p = tf32r(__expf(s[nt][1] - mn0)); s[nt][1] = p; rs0 += p;
            p = tf32r(__expf(s[nt][2] - mn1)); s[nt][2] = p; rs1 += p;
            p = tf32r(__expf(s[nt][3] - mn1)); s[nt][3] = p; rs1 += p;
        }
        rs0 += __shfl_xor_sync(0xffffffffu, rs0, 1);
        rs0 += __shfl_xor_sync(0xffffffffu, rs0, 2);
        rs1 += __shfl_xor_sync(0xffffffffu, rs1, 1);
        rs1 += __shfl_xor_sync(0xffffffffu, rs1, 2);
        l0 = l0 * c0 + rs0;
        l1 = l1 * c1 + rs1;
#pragma unroll
        for (int nt = 0; nt < 8; nt++) {
            o[nt][0] *= c0; o[nt][1] *= c0;
            o[nt][2] *= c1; o[nt][3] *= c1;
        }

        // ---- O += P V : P C-frag -> A-frag via quad shuffles ----
        const int src1 = (lane & ~3) | (g >> 1);
        const int src2 = src1 + 2;
        const bool odd = (g & 1) != 0;
#pragma unroll
        for (int kt = 0; kt < 8; kt++) {
            float x0 = __shfl_sync(0xffffffffu, s[kt][0], src1);
            float x1 = __shfl_sync(0xffffffffu, s[kt][1], src1);
            float y0 = __shfl_sync(0xffffffffu, s[kt][2], src1);
            float y1 = __shfl_sync(0xffffffffu, s[kt][3], src1);
            float z0 = __shfl_sync(0xffffffffu, s[kt][0], src2);
            float z1 = __shfl_sync(0xffffffffu, s[kt][1], src2);
            float w0 = __shfl_sync(0xffffffffu, s[kt][2], src2);
            float w1 = __shfl_sync(0xffffffffu, s[kt][3], src2);
            float a[4];
            a[0] = odd ? x1 : x0;   // P[row r  ][key kt*8+g]
            a[1] = odd ? y1 : y0;   // P[row r+8][key kt*8+g]
            a[2] = odd ? z1 : z0;   // P[row r  ][key kt*8+g+4]
            a[3] = odd ? w1 : w0;   // P[row r+8][key kt*8+g+4]

            float vh[8][2], vl[8][2];
#pragma unroll
            for (int nt = 0; nt < 8; nt++) {
                vh[nt][0] = Vh[kt * 8 + g][nt * 8 + r];
                vh[nt][1] = Vh[kt * 8 + g + 4][nt * 8 + r];
                vl[nt][0] = Vl[kt * 8 + g][nt * 8 + r];
                vl[nt][1] = Vl[kt * 8 + g + 4][nt * 8 + r];
            }
#pragma unroll
            for (int nt = 0; nt < 8; nt++) mma_f(o[nt], a, vh[nt][0], vh[nt][1]);
#pragma unroll
            for (int nt = 0; nt < 8; nt++) mma_f(o[nt], a, vl[nt][0], vl[nt][1]);
        }
    }

    // ---- normalize + store [B,H,T,HD] ----
    float inv0 = 1.f / l0, inv1 = 1.f / l1;
    float* ob = ao + ((size_t)bh * NT + q0 + wr) * NHD;
#pragma unroll
    for (int nt = 0; nt < 8; nt++) {
        int col = nt * 8 + 2 * g;
        *(float2*)(ob + (size_t)r * NHD + col) =
            make_float2(o[nt][0] * inv0, o[nt][1] * inv0);
        *(float2*)(ob + (size_t)(r + 8) * NHD + col) =
            make_float2(o[nt][2] * inv1, o[nt][3] * inv1);
    }
}

// ---------------------------------------------------------------------------
extern "C" void kernel_launch(void* const* d_in, const int* in_sizes, int n_in,
                              void* d_out, int out_size)
{
    const float* q  = (const float*)d_in[0];
    const float* k  = (const float*)d_in[1];
    const float* v  = (const float*)d_in[2];
    const float* Wq = (const float*)d_in[3];
    const float* bq = (const float*)d_in[4];
    const float* Wk = (const float*)d_in[5];
    const float* bk = (const float*)d_in[6];
    const float* Wv = (const float*)d_in[7];
    const float* bv = (const float*)d_in[8];
    const float* Wo = (const float*)d_in[9];
    const float* bo = (const float*)d_in[10];
    float* out = (float*)d_out;

    float *pq, *pkt, *pv, *po;
    cudaGetSymbolAddress((void**)&pq,  g_q);
    cudaGetSymbolAddress((void**)&pkt, g_kt);
    cudaGetSymbolAddress((void**)&pv,  g_v);
    cudaGetSymbolAddress((void**)&po,  g_o);

    const int gemm_smem = 65536;
    cudaFuncSetAttribute(gemm_tc<0,0>, cudaFuncAttributeMaxDynamicSharedMemorySize, gemm_smem);
    cudaFuncSetAttribute(gemm_tc<0,1>, cudaFuncAttributeMaxDynamicSharedMemorySize, gemm_smem);
    cudaFuncSetAttribute(gemm_tc<1,2>, cudaFuncAttributeMaxDynamicSharedMemorySize, gemm_smem);

    dim3 gg(ND / 128, NM / 128);   // (8, 64)

    gemm_tc<0, 0><<<gg, 256, gemm_smem>>>(q, Wq, bq, pq);
    gemm_tc<0, 1><<<gg, 256, gemm_smem>>>(k, Wk, bk, pkt);   // K proj + transpose fused
    gemm_tc<0, 0><<<gg, 256, gemm_smem>>>(v, Wv, bv, pv);

    const int attn_smem = 6 * 64 * 68 * (int)sizeof(float);  // 104,448 B
    cudaFuncSetAttribute(attn_mma, cudaFuncAttributeMaxDynamicSharedMemorySize, attn_smem);
    attn_mma<<<dim3(NT / 64, NB * NH), 128, attn_smem>>>(pq, pkt, pv, po);

    gemm_tc<1, 2><<<gg, 256, gemm_smem>>>(po, Wo, bo, out);
}

// round 6
// speedup vs baseline: 1.8541x; 1.1789x over previous
#include <cuda_runtime.h>
#include <cstdint>

#define NB 4
#define NT 2048
#define ND 1024
#define NH 16
#define NHD 64
#define NM (NB*NT)   // 8192 rows

// Scratch (allocation-free rule: __device__ globals).
__device__ float g_q [NB*NH*NT*NHD];   // [B,H,T,HD]
__device__ float g_kt[NB*NH*NHD*NT];   // [B,H,HD,T]  (K projected + transposed)
__device__ float g_v [NB*NH*NT*NHD];   // [B,H,T,HD]
__device__ float g_o [NB*NH*NT*NHD];   // [B,H,T,HD] attention output

__device__ __forceinline__ unsigned f2tf(float f) {
    unsigned u;
    asm("cvt.rna.tf32.f32 %0, %1;" : "=r"(u) : "f"(f));
    return u;
}
__device__ __forceinline__ float tf32r(float f) { return __uint_as_float(f2tf(f)); }

__device__ __forceinline__ void mma_tf32(float c[4], const unsigned a[4], const unsigned b[2]) {
    asm volatile(
        "mma.sync.aligned.m16n8k8.row.col.f32.tf32.tf32.f32 "
        "{%0,%1,%2,%3}, {%4,%5,%6,%7}, {%8,%9}, {%0,%1,%2,%3};"
        : "+f"(c[0]), "+f"(c[1]), "+f"(c[2]), "+f"(c[3])
        : "r"(a[0]), "r"(a[1]), "r"(a[2]), "r"(a[3]), "r"(b[0]), "r"(b[1]));
}
__device__ __forceinline__ void mma_f(float c[4], const float a[4], const float b0, const float b1) {
    asm volatile(
        "mma.sync.aligned.m16n8k8.row.col.f32.tf32.tf32.f32 "
        "{%0,%1,%2,%3}, {%4,%5,%6,%7}, {%8,%9}, {%0,%1,%2,%3};"
        : "+f"(c[0]), "+f"(c[1]), "+f"(c[2]), "+f"(c[3])
        : "r"(__float_as_uint(a[0])), "r"(__float_as_uint(a[1])),
          "r"(__float_as_uint(a[2])), "r"(__float_as_uint(a[3])),
          "r"(__float_as_uint(b0)),   "r"(__float_as_uint(b1)));
}

// ---------------------------------------------------------------------------
// Tensor-core tf32 GEMM (verbatim from passing R3/R5): C = A @ W^T + bias.
// ---------------------------------------------------------------------------
template<int AMODE, int OMODE>
__global__ __launch_bounds__(256)
void gemm_tc(const float* __restrict__ A, const float* __restrict__ W,
             const float* __restrict__ bias, float* __restrict__ Cout)
{
    extern __shared__ unsigned sh[];
    unsigned* As = sh;           // 2 bufs x 4096 u32
    unsigned* Ws = sh + 8192;

    const int tid  = threadIdx.x;
    const int lane = tid & 31;
    const int warp = tid >> 5;
    const int wm   = warp & 1;
    const int wn   = warp >> 1;
    const int bm   = blockIdx.y * 128;
    const int bn   = blockIdx.x * 128;

    float acc[4][4][4];
#pragma unroll
    for (int mi = 0; mi < 4; mi++)
#pragma unroll
        for (int nj = 0; nj < 4; nj++)
#pragma unroll
            for (int r = 0; r < 4; r++) acc[mi][nj][r] = 0.f;

    float4 ar[4], wr[4];

    auto ldg = [&](int s) {
#pragma unroll
        for (int l = 0; l < 4; l++) {
            int idx = l * 256 + tid;
            int row = idx >> 3;
            int kq  = idx & 7;
            int kg  = s * 32 + kq * 4;
            if (AMODE == 0) {
                ar[l] = *(const float4*)(A + (size_t)(bm + row) * ND + kg);
            } else {
                int m  = bm + row;
                int b_ = m >> 11, t_ = m & (NT - 1);
                int h_ = kg >> 6, hd = kg & 63;
                ar[l] = *(const float4*)(A + (((size_t)(b_ * NH + h_) * NT + t_) * NHD + hd));
            }
            wr[l] = *(const float4*)(W + (size_t)(bn + row) * ND + kg);
        }
    };

    auto sts = [&](int buf) {
        unsigned* ab = As + buf * 4096;
        unsigned* wb = Ws + buf * 4096;
#pragma unroll
        for (int l = 0; l < 4; l++) {
            int idx = l * 256 + tid;
            int row = idx >> 3;
            int kq  = idx & 7;
            {
                unsigned* p = ab + (((row >> 4) * 4 + (kq >> 1)) << 7);
                int reg = ((kq & 1) << 1) + ((row >> 3) & 1);
                int lb  = (row & 7) * 4;
                p[(lb + 0) * 4 + reg] = f2tf(ar[l].x);
                p[(lb + 1) * 4 + reg] = f2tf(ar[l].y);
                p[(lb + 2) * 4 + reg] = f2tf(ar[l].z);
                p[(lb + 3) * 4 + reg] = f2tf(ar[l].w);
            }
            {
                unsigned* p = wb + (((row >> 3) * 4 + (kq >> 1)) << 6);
                int reg = (kq & 1);
                int lb  = (row & 7) * 4;
                p[(lb + 0) * 2 + reg] = f2tf(wr[l].x);
                p[(lb + 1) * 2 + reg] = f2tf(wr[l].y);
                p[(lb + 2) * 2 + reg] = f2tf(wr[l].z);
                p[(lb + 3) * 2 + reg] = f2tf(wr[l].w);
            }
        }
    };

    auto compute = [&](int buf) {
        const unsigned* ab = As + buf * 4096;
        const unsigned* wb = Ws + buf * 4096;
#pragma unroll
        for (int kt = 0; kt < 4; kt++) {
            unsigned af[4][4];
#pragma unroll
            for (int mi = 0; mi < 4; mi++) {
                uint4 t = *(const uint4*)(ab + ((((wm * 4 + mi) * 4 + kt)) << 7) + (lane << 2));
                af[mi][0] = t.x; af[mi][1] = t.y; af[mi][2] = t.z; af[mi][3] = t.w;
            }
            unsigned bf[4][2];
#pragma unroll
            for (int nj = 0; nj < 4; nj++) {
                uint2 t = *(const uint2*)(wb + ((((wn * 4 + nj) * 4 + kt)) << 6) + (lane << 1));
                bf[nj][0] = t.x; bf[nj][1] = t.y;
            }
#pragma unroll
            for (int mi = 0; mi < 4; mi++)
#pragma unroll
                for (int nj = 0; nj < 4; nj++)
                    mma_tf32(acc[mi][nj], af[mi], bf[nj]);
        }
    };

    ldg(0);
    sts(0);
    __syncthreads();
    for (int s = 0; s < 32; s++) {
        int buf = s & 1;
        if (s < 31) ldg(s + 1);
        compute(buf);
        if (s < 31) sts(buf ^ 1);
        __syncthreads();
    }

#pragma unroll
    for (int nj = 0; nj < 4; nj++) {
        int col = bn + (wn * 4 + nj) * 8 + (lane & 3) * 2;
        float b0 = bias[col], b1 = bias[col + 1];
#pragma unroll
        for (int mi = 0; mi < 4; mi++) {
            int row = bm + (wm * 4 + mi) * 16 + (lane >> 2);
            float v00 = acc[mi][nj][0] + b0, v01 = acc[mi][nj][1] + b1;
            float v10 = acc[mi][nj][2] + b0, v11 = acc[mi][nj][3] + b1;
            if (OMODE == 2) {
                *(float2*)(Cout + (size_t)row * ND + col)       = make_float2(v00, v01);
                *(float2*)(Cout + (size_t)(row + 8) * ND + col) = make_float2(v10, v11);
            } else if (OMODE == 0) {
                int b_ = row >> 11, t_ = row & (NT - 1);
                int h_ = col >> 6, hd = col & 63;
                float* p = Cout + (((size_t)(b_ * NH + h_) * NT + t_) * NHD + hd);
                *(float2*)p             = make_float2(v00, v01);
                *(float2*)(p + 8 * NHD) = make_float2(v10, v11);
            } else { // OMODE 1: [B,H,HD,T]
                int b_ = row >> 11, t_ = row & (NT - 1);
                int h_ = col >> 6, hd = col & 63;
                float* p = Cout + (((size_t)(b_ * NH + h_) * NHD + hd) * NT + t_);
                p[0]      = v00;
                p[NT]     = v01;
                p[8]      = v10;
                p[NT + 8] = v11;
            }
        }
    }
}

// ---------------------------------------------------------------------------
// Flash attention v2 on tf32 mma.sync.
// 128 threads = 4 warps; CTA = 128 queries; warp owns 32 rows (2 m16 tiles).
// Pitch 72 floats -> ALL fragment LDS conflict-free (A: bank 8r+g, B: 8g+r).
// S = qh*kh + qh*kl + ql*kh (3 chains); PV = p*vh (single; V tf32-rounded).
// smem: Qh,Ql [128][72]; Kh,Kl [64][72] (rows=hd, cols=key); Vh [64][72].
// ---------------------------------------------------------------------------
__global__ __launch_bounds__(128)
void attn_mma(const float* __restrict__ qp, const float* __restrict__ ktp,
              const float* __restrict__ vp, float* __restrict__ ao)
{
    extern __shared__ float smf[];
    float (*Qh)[72] = (float (*)[72])(smf);
    float (*Ql)[72] = (float (*)[72])(smf + 128 * 72);
    float (*Kh)[72] = (float (*)[72])(smf + 2 * 128 * 72);
    float (*Kl)[72] = (float (*)[72])(smf + 2 * 128 * 72 + 64 * 72);
    float (*Vh)[72] = (float (*)[72])(smf + 2 * 128 * 72 + 2 * 64 * 72);

    const int tid  = threadIdx.x;
    const int lane = tid & 31;
    const int warp = tid >> 5;
    const int wr   = warp * 32;          // warp's row base in the 128-q tile
    const int r    = lane >> 2;          // 0..7
    const int g    = lane & 3;           // 0..3
    const int bh   = blockIdx.y;
    const int q0   = blockIdx.x * 128;

    const float* qb = qp  + ((size_t)bh * NT + q0) * NHD;
    const float* kb = ktp + (size_t)bh * NHD * NT;
    const float* vb = vp  + (size_t)bh * NT * NHD;

    // Stage Q (hi/lo) once: 128 rows x 16 float4.
#pragma unroll
    for (int i = 0; i < 16; i++) {
        int idx = i * 128 + tid;
        int row = idx >> 4, f4 = idx & 15;
        float4 x = *(const float4*)(qb + row * NHD + f4 * 4);
        float4 h = make_float4(tf32r(x.x), tf32r(x.y), tf32r(x.z), tf32r(x.w));
        float4 l = make_float4(tf32r(x.x - h.x), tf32r(x.y - h.y),
                               tf32r(x.z - h.z), tf32r(x.w - h.w));
        *(float4*)&Qh[row][f4 * 4] = h;
        *(float4*)&Ql[row][f4 * 4] = l;
    }

    float o[2][8][4];
    float m0[2], m1[2], l0[2], l1[2];
#pragma unroll
    for (int mt = 0; mt < 2; mt++) {
        m0[mt] = -1e30f; m1[mt] = -1e30f; l0[mt] = 0.f; l1[mt] = 0.f;
#pragma unroll
        for (int nt = 0; nt < 8; nt++)
#pragma unroll
            for (int c = 0; c < 4; c++) o[mt][nt][c] = 0.f;
    }

    for (int t0 = 0; t0 < NT; t0 += 64) {
        __syncthreads();   // prev compute done before restaging (covers Q on iter 0)
#pragma unroll
        for (int i = 0; i < 8; i++) {
            int idx = i * 128 + tid;
            int row = idx >> 4, f4 = idx & 15;
            {
                float4 x = *(const float4*)(kb + (size_t)row * NT + t0 + f4 * 4);
                float4 h = make_float4(tf32r(x.x), tf32r(x.y), tf32r(x.z), tf32r(x.w));
                float4 l = make_float4(tf32r(x.x - h.x), tf32r(x.y - h.y),
                                       tf32r(x.z - h.z), tf32r(x.w - h.w));
                *(float4*)&Kh[row][f4 * 4] = h;
                *(float4*)&Kl[row][f4 * 4] = l;
            }
            {
                float4 x = *(const float4*)(vb + (size_t)(t0 + row) * NHD + f4 * 4);
                *(float4*)&Vh[row][f4 * 4] =
                    make_float4(tf32r(x.x), tf32r(x.y), tf32r(x.z), tf32r(x.w));
            }
        }
        __syncthreads();

        // ---- S = Q K^T : 2 m-tiles x 8 n-tiles x 8 k-tiles, 3 chains ----
        float s[2][8][4];
#pragma unroll
        for (int mt = 0; mt < 2; mt++)
#pragma unroll
            for (int nt = 0; nt < 8; nt++)
#pragma unroll
                for (int c = 0; c < 4; c++) s[mt][nt][c] = 0.f;

#pragma unroll
        for (int kt = 0; kt < 8; kt++) {
            float ah[2][4], al[2][4];
#pragma unroll
            for (int mt = 0; mt < 2; mt++) {
                int base = wr + mt * 16;
                ah[mt][0] = Qh[base + r][kt * 8 + g];         al[mt][0] = Ql[base + r][kt * 8 + g];
                ah[mt][1] = Qh[base + r + 8][kt * 8 + g];     al[mt][1] = Ql[base + r + 8][kt * 8 + g];
                ah[mt][2] = Qh[base + r][kt * 8 + g + 4];     al[mt][2] = Ql[base + r][kt * 8 + g + 4];
                ah[mt][3] = Qh[base + r + 8][kt * 8 + g + 4]; al[mt][3] = Ql[base + r + 8][kt * 8 + g + 4];
            }
            float bhf[8][2], blf[8][2];
#pragma unroll
            for (int nt = 0; nt < 8; nt++) {
                bhf[nt][0] = Kh[kt * 8 + g][nt * 8 + r];
                bhf[nt][1] = Kh[kt * 8 + g + 4][nt * 8 + r];
                blf[nt][0] = Kl[kt * 8 + g][nt * 8 + r];
                blf[nt][1] = Kl[kt * 8 + g + 4][nt * 8 + r];
            }
#pragma unroll
            for (int mt = 0; mt < 2; mt++)
#pragma unroll
                for (int nt = 0; nt < 8; nt++) mma_f(s[mt][nt], ah[mt], bhf[nt][0], bhf[nt][1]);
#pragma unroll
            for (int mt = 0; mt < 2; mt++)
#pragma unroll
                for (int nt = 0; nt < 8; nt++) mma_f(s[mt][nt], ah[mt], blf[nt][0], blf[nt][1]);
#pragma unroll
            for (int mt = 0; mt < 2; mt++)
#pragma unroll
                for (int nt = 0; nt < 8; nt++) mma_f(s[mt][nt], al[mt], bhf[nt][0], bhf[nt][1]);
        }

        // ---- online softmax per m-tile (rows r, r+8; quad-wide reductions) ----
#pragma unroll
        for (int mt = 0; mt < 2; mt++) {
            float mx0 = -1e30f, mx1 = -1e30f;
#pragma unroll
            for (int nt = 0; nt < 8; nt++) {
                s[mt][nt][0] *= 0.125f; s[mt][nt][1] *= 0.125f;
                s[mt][nt][2] *= 0.125f; s[mt][nt][3] *= 0.125f;
                mx0 = fmaxf(mx0, fmaxf(s[mt][nt][0], s[mt][nt][1]));
                mx1 = fmaxf(mx1, fmaxf(s[mt][nt][2], s[mt][nt][3]));
            }
            mx0 = fmaxf(mx0, __shfl_xor_sync(0xffffffffu, mx0, 1));
            mx0 = fmaxf(mx0, __shfl_xor_sync(0xffffffffu, mx0, 2));
            mx1 = fmaxf(mx1, __shfl_xor_sync(0xffffffffu, mx1, 1));
            mx1 = fmaxf(mx1, __shfl_xor_sync(0xffffffffu, mx1, 2));

            float mn0 = fmaxf(m0[mt], mx0), mn1 = fmaxf(m1[mt], mx1);
            float c0 = __expf(m0[mt] - mn0), c1 = __expf(m1[mt] - mn1);
            m0[mt] = mn0; m1[mt] = mn1;

            float rs0 = 0.f, rs1 = 0.f;
#pragma unroll
            for (int nt = 0; nt < 8; nt++) {
                float p;
                p = tf32r(__expf(s[mt][nt][0] - mn0)); s[mt][nt][0] = p; rs0 += p;
                p = tf32r(__expf(s[mt][nt][1] - mn0)); s[mt][nt][1] = p; rs0 += p;
                p = tf32r(__expf(s[mt][nt][2] - mn1)); s[mt][nt][2] = p; rs1 += p;
                p = tf32r(__expf(s[mt][nt][3] - mn1)); s[mt][nt][3] = p; rs1 += p;
            }
            rs0 += __shfl_xor_sync(0xffffffffu, rs0, 1);
            rs0 += __shfl_xor_sync(0xffffffffu, rs0, 2);
            rs1 += __shfl_xor_sync(0xffffffffu, rs1, 1);
            rs1 += __shfl_xor_sync(0xffffffffu, rs1, 2);
            l0[mt] = l0[mt] * c0 + rs0;
            l1[mt] = l1[mt] * c1 + rs1;
#pragma unroll
            for (int nt = 0; nt < 8; nt++) {
                o[mt][nt][0] *= c0; o[mt][nt][1] *= c0;
                o[mt][nt][2] *= c1; o[mt][nt][3] *= c1;
            }
        }

        // ---- O += P V : P C-frag -> A-frag via quad shuffles; single V chain ----
        const int src1 = (lane & ~3) | (g >> 1);
        const int src2 = src1 + 2;
        const bool odd = (g & 1) != 0;
#pragma unroll
        for (int kt = 0; kt < 8; kt++) {
            float a[2][4];
#pragma unroll
            for (int mt = 0; mt < 2; mt++) {
                float x0 = __shfl_sync(0xffffffffu, s[mt][kt][0], src1);
                float x1 = __shfl_sync(0xffffffffu, s[mt][kt][1], src1);
                float y0 = __shfl_sync(0xffffffffu, s[mt][kt][2], src1);
                float y1 = __shfl_sync(0xffffffffu, s[mt][kt][3], src1);
                float z0 = __shfl_sync(0xffffffffu, s[mt][kt][0], src2);
                float z1 = __shfl_sync(0xffffffffu, s[mt][kt][1], src2);
                float w0 = __shfl_sync(0xffffffffu, s[mt][kt][2], src2);
                float w1 = __shfl_sync(0xffffffffu, s[mt][kt][3], src2);
                a[mt][0] = odd ? x1 : x0;
                a[mt][1] = odd ? y1 : y0;
                a[mt][2] = odd ? z1 : z0;
                a[mt][3] = odd ? w1 : w0;
            }
            float vv[8][2];
#pragma unroll
            for (int nt = 0; nt < 8; nt++) {
                vv[nt][0] = Vh[kt * 8 + g][nt * 8 + r];
                vv[nt][1] = Vh[kt * 8 + g + 4][nt * 8 + r];
            }
#pragma unroll
            for (int mt = 0; mt < 2; mt++)
#pragma unroll
                for (int nt = 0; nt < 8; nt++) mma_f(o[mt][nt], a[mt], vv[nt][0], vv[nt][1]);
        }
    }

    // ---- normalize + store [B,H,T,HD] ----
#pragma unroll
    for (int mt = 0; mt < 2; mt++) {
        float inv0 = 1.f / l0[mt], inv1 = 1.f / l1[mt];
        float* ob = ao + ((size_t)bh * NT + q0 + wr + mt * 16) * NHD;
#pragma unroll
        for (int nt = 0; nt < 8; nt++) {
            int col = nt * 8 + 2 * g;
            *(float2*)(ob + (size_t)r * NHD + col) =
                make_float2(o[mt][nt][0] * inv0, o[mt][nt][1] * inv0);
            *(float2*)(ob + (size_t)(r + 8) * NHD + col) =
                make_float2(o[mt][nt][2] * inv1, o[mt][nt][3] * inv1);
        }
    }
}

// ---------------------------------------------------------------------------
extern "C" void kernel_launch(void* const* d_in, const int* in_sizes, int n_in,
                              void* d_out, int out_size)
{
    const float* q  = (const float*)d_in[0];
    const float* k  = (const float*)d_in[1];
    const float* v  = (const float*)d_in[2];
    const float* Wq = (const float*)d_in[3];
    const float* bq = (const float*)d_in[4];
    const float* Wk = (const float*)d_in[5];
    const float* bk = (const float*)d_in[6];
    const float* Wv = (const float*)d_in[7];
    const float* bv = (const float*)d_in[8];
    const float* Wo = (const float*)d_in[9];
    const float* bo = (const float*)d_in[10];
    float* out = (float*)d_out;

    float *pq, *pkt, *pv, *po;
    cudaGetSymbolAddress((void**)&pq,  g_q);
    cudaGetSymbolAddress((void**)&pkt, g_kt);
    cudaGetSymbolAddress((void**)&pv,  g_v);
    cudaGetSymbolAddress((void**)&po,  g_o);

    const int gemm_smem = 65536;
    cudaFuncSetAttribute(gemm_tc<0,0>, cudaFuncAttributeMaxDynamicSharedMemorySize, gemm_smem);
    cudaFuncSetAttribute(gemm_tc<0,1>, cudaFuncAttributeMaxDynamicSharedMemorySize, gemm_smem);
    cudaFuncSetAttribute(gemm_tc<1,2>, cudaFuncAttributeMaxDynamicSharedMemorySize, gemm_smem);

    dim3 gg(ND / 128, NM / 128);   // (8, 64)

    gemm_tc<0, 0><<<gg, 256, gemm_smem>>>(q, Wq, bq, pq);
    gemm_tc<0, 1><<<gg, 256, gemm_smem>>>(k, Wk, bk, pkt);   // K proj + transpose fused
    gemm_tc<0, 0><<<gg, 256, gemm_smem>>>(v, Wv, bv, pv);

    // smem: Qh+Ql (2*128*72) + Kh+Kl (2*64*72) + Vh (64*72) floats = 129,024 B
    const int attn_smem = (2 * 128 + 2 * 64 + 64) * 72 * (int)sizeof(float);
    cudaFuncSetAttribute(attn_mma, cudaFuncAttributeMaxDynamicSharedMemorySize, attn_smem);
    attn_mma<<<dim3(NT / 128, NB * NH), 128, attn_smem>>>(pq, pkt, pv, po);

    gemm_tc<1, 2><<<gg, 256, gemm_smem>>>(po, Wo, bo, out);
}

// round 7
// speedup vs baseline: 1.9722x; 1.0637x over previous
#include <cuda_runtime.h>
#include <cstdint>

#define NB 4
#define NT 2048
#define ND 1024
#define NH 16
#define NHD 64
#define NM (NB*NT)   // 8192 rows

// Scratch (allocation-free rule: __device__ globals).
__device__ float g_q [NB*NH*NT*NHD];   // [B,H,T,HD]
__device__ float g_kt[NB*NH*NHD*NT];   // [B,H,HD,T]  (K projected + transposed)
__device__ float g_v [NB*NH*NT*NHD];   // [B,H,T,HD]
__device__ float g_o [NB*NH*NT*NHD];   // [B,H,T,HD] attention output

__device__ __forceinline__ unsigned f2tf(float f) {
    unsigned u;
    asm("cvt.rna.tf32.f32 %0, %1;" : "=r"(u) : "f"(f));
    return u;
}
__device__ __forceinline__ float tf32r(float f) { return __uint_as_float(f2tf(f)); }

__device__ __forceinline__ void mma_tf32(float c[4], const unsigned a[4], const unsigned b[2]) {
    asm volatile(
        "mma.sync.aligned.m16n8k8.row.col.f32.tf32.tf32.f32 "
        "{%0,%1,%2,%3}, {%4,%5,%6,%7}, {%8,%9}, {%0,%1,%2,%3};"
        : "+f"(c[0]), "+f"(c[1]), "+f"(c[2]), "+f"(c[3])
        : "r"(a[0]), "r"(a[1]), "r"(a[2]), "r"(a[3]), "r"(b[0]), "r"(b[1]));
}
__device__ __forceinline__ void mma_f(float c[4], const float a[4], const float b0, const float b1) {
    asm volatile(
        "mma.sync.aligned.m16n8k8.row.col.f32.tf32.tf32.f32 "
        "{%0,%1,%2,%3}, {%4,%5,%6,%7}, {%8,%9}, {%0,%1,%2,%3};"
        : "+f"(c[0]), "+f"(c[1]), "+f"(c[2]), "+f"(c[3])
        : "r"(__float_as_uint(a[0])), "r"(__float_as_uint(a[1])),
          "r"(__float_as_uint(a[2])), "r"(__float_as_uint(a[3])),
          "r"(__float_as_uint(b0)),   "r"(__float_as_uint(b1)));
}

// ---------------------------------------------------------------------------
// Tensor-core tf32 GEMM (verbatim from passing R3/R5/R6): C = A @ W^T + bias.
// ---------------------------------------------------------------------------
template<int AMODE, int OMODE>
__global__ __launch_bounds__(256)
void gemm_tc(const float* __restrict__ A, const float* __restrict__ W,
             const float* __restrict__ bias, float* __restrict__ Cout)
{
    extern __shared__ unsigned sh[];
    unsigned* As = sh;           // 2 bufs x 4096 u32
    unsigned* Ws = sh + 8192;

    const int tid  = threadIdx.x;
    const int lane = tid & 31;
    const int warp = tid >> 5;
    const int wm   = warp & 1;
    const int wn   = warp >> 1;
    const int bm   = blockIdx.y * 128;
    const int bn   = blockIdx.x * 128;

    float acc[4][4][4];
#pragma unroll
    for (int mi = 0; mi < 4; mi++)
#pragma unroll
        for (int nj = 0; nj < 4; nj++)
#pragma unroll
            for (int r = 0; r < 4; r++) acc[mi][nj][r] = 0.f;

    float4 ar[4], wr[4];

    auto ldg = [&](int s) {
#pragma unroll
        for (int l = 0; l < 4; l++) {
            int idx = l * 256 + tid;
            int row = idx >> 3;
            int kq  = idx & 7;
            int kg  = s * 32 + kq * 4;
            if (AMODE == 0) {
                ar[l] = *(const float4*)(A + (size_t)(bm + row) * ND + kg);
            } else {
                int m  = bm + row;
                int b_ = m >> 11, t_ = m & (NT - 1);
                int h_ = kg >> 6, hd = kg & 63;
                ar[l] = *(const float4*)(A + (((size_t)(b_ * NH + h_) * NT + t_) * NHD + hd));
            }
            wr[l] = *(const float4*)(W + (size_t)(bn + row) * ND + kg);
        }
    };

    auto sts = [&](int buf) {
        unsigned* ab = As + buf * 4096;
        unsigned* wb = Ws + buf * 4096;
#pragma unroll
        for (int l = 0; l < 4; l++) {
            int idx = l * 256 + tid;
            int row = idx >> 3;
            int kq  = idx & 7;
            {
                unsigned* p = ab + (((row >> 4) * 4 + (kq >> 1)) << 7);
                int reg = ((kq & 1) << 1) + ((row >> 3) & 1);
                int lb  = (row & 7) * 4;
                p[(lb + 0) * 4 + reg] = f2tf(ar[l].x);
                p[(lb + 1) * 4 + reg] = f2tf(ar[l].y);
                p[(lb + 2) * 4 + reg] = f2tf(ar[l].z);
                p[(lb + 3) * 4 + reg] = f2tf(ar[l].w);
            }
            {
                unsigned* p = wb + (((row >> 3) * 4 + (kq >> 1)) << 6);
                int reg = (kq & 1);
                int lb  = (row & 7) * 4;
                p[(lb + 0) * 2 + reg] = f2tf(wr[l].x);
                p[(lb + 1) * 2 + reg] = f2tf(wr[l].y);
                p[(lb + 2) * 2 + reg] = f2tf(wr[l].z);
                p[(lb + 3) * 2 + reg] = f2tf(wr[l].w);
            }
        }
    };

    auto compute = [&](int buf) {
        const unsigned* ab = As + buf * 4096;
        const unsigned* wb = Ws + buf * 4096;
#pragma unroll
        for (int kt = 0; kt < 4; kt++) {
            unsigned af[4][4];
#pragma unroll
            for (int mi = 0; mi < 4; mi++) {
                uint4 t = *(const uint4*)(ab + ((((wm * 4 + mi) * 4 + kt)) << 7) + (lane << 2));
                af[mi][0] = t.x; af[mi][1] = t.y; af[mi][2] = t.z; af[mi][3] = t.w;
            }
            unsigned bf[4][2];
#pragma unroll
            for (int nj = 0; nj < 4; nj++) {
                uint2 t = *(const uint2*)(wb + ((((wn * 4 + nj) * 4 + kt)) << 6) + (lane << 1));
                bf[nj][0] = t.x; bf[nj][1] = t.y;
            }
#pragma unroll
            for (int mi = 0; mi < 4; mi++)
#pragma unroll
                for (int nj = 0; nj < 4; nj++)
                    mma_tf32(acc[mi][nj], af[mi], bf[nj]);
        }
    };

    ldg(0);
    sts(0);
    __syncthreads();
    for (int s = 0; s < 32; s++) {
        int buf = s & 1;
        if (s < 31) ldg(s + 1);
        compute(buf);
        if (s < 31) sts(buf ^ 1);
        __syncthreads();
    }

#pragma unroll
    for (int nj = 0; nj < 4; nj++) {
        int col = bn + (wn * 4 + nj) * 8 + (lane & 3) * 2;
        float b0 = bias[col], b1 = bias[col + 1];
#pragma unroll
        for (int mi = 0; mi < 4; mi++) {
            int row = bm + (wm * 4 + mi) * 16 + (lane >> 2);
            float v00 = acc[mi][nj][0] + b0, v01 = acc[mi][nj][1] + b1;
            float v10 = acc[mi][nj][2] + b0, v11 = acc[mi][nj][3] + b1;
            if (OMODE == 2) {
                *(float2*)(Cout + (size_t)row * ND + col)       = make_float2(v00, v01);
                *(float2*)(Cout + (size_t)(row + 8) * ND + col) = make_float2(v10, v11);
            } else if (OMODE == 0) {
                int b_ = row >> 11, t_ = row & (NT - 1);
                int h_ = col >> 6, hd = col & 63;
                float* p = Cout + (((size_t)(b_ * NH + h_) * NT + t_) * NHD + hd);
                *(float2*)p             = make_float2(v00, v01);
                *(float2*)(p + 8 * NHD) = make_float2(v10, v11);
            } else { // OMODE 1: [B,H,HD,T]
                int b_ = row >> 11, t_ = row & (NT - 1);
                int h_ = col >> 6, hd = col & 63;
                float* p = Cout + (((size_t)(b_ * NH + h_) * NHD + hd) * NT + t_);
                p[0]      = v00;
                p[NT]     = v01;
                p[8]      = v10;
                p[NT + 8] = v11;
            }
        }
    }
}

// ---------------------------------------------------------------------------
// Flash attention v3: 256 threads = 8 warps; CTA = 128 queries; warp owns
// 16 rows (one m16 tile). Pitch 72 -> all fragment LDS conflict-free.
// S = qh*kh + qh*kl + ql*kh; PV = p*vh. Same math as R6 (rel_err ~6.5e-4).
// smem: Qh,Ql [128][72]; Kh,Kl [64][72] (rows=hd, cols=key); Vh [64][72].
// ---------------------------------------------------------------------------
__global__ __launch_bounds__(256)
void attn_mma(const float* __restrict__ qp, const float* __restrict__ ktp,
              const float* __restrict__ vp, float* __restrict__ ao)
{
    extern __shared__ float smf[];
    float (*Qh)[72] = (float (*)[72])(smf);
    float (*Ql)[72] = (float (*)[72])(smf + 128 * 72);
    float (*Kh)[72] = (float (*)[72])(smf + 2 * 128 * 72);
    float (*Kl)[72] = (float (*)[72])(smf + 2 * 128 * 72 + 64 * 72);
    float (*Vh)[72] = (float (*)[72])(smf + 2 * 128 * 72 + 2 * 64 * 72);

    const int tid  = threadIdx.x;
    const int lane = tid & 31;
    const int warp = tid >> 5;
    const int wr   = warp * 16;          // warp's row base in the 128-q tile
    const int r    = lane >> 2;          // 0..7
    const int g    = lane & 3;           // 0..3
    const int bh   = blockIdx.y;
    const int q0   = blockIdx.x * 128;

    const float* qb = qp  + ((size_t)bh * NT + q0) * NHD;
    const float* kb = ktp + (size_t)bh * NHD * NT;
    const float* vb = vp  + (size_t)bh * NT * NHD;

    // Stage Q (hi/lo) once: 128 rows x 16 float4 = 2048 float4.
#pragma unroll
    for (int i = 0; i < 8; i++) {
        int idx = i * 256 + tid;
        int row = idx >> 4, f4 = idx & 15;
        float4 x = *(const float4*)(qb + row * NHD + f4 * 4);
        float4 h = make_float4(tf32r(x.x), tf32r(x.y), tf32r(x.z), tf32r(x.w));
        float4 l = make_float4(tf32r(x.x - h.x), tf32r(x.y - h.y),
                               tf32r(x.z - h.z), tf32r(x.w - h.w));
        *(float4*)&Qh[row][f4 * 4] = h;
        *(float4*)&Ql[row][f4 * 4] = l;
    }

    float o[8][4];
#pragma unroll
    for (int nt = 0; nt < 8; nt++)
#pragma unroll
        for (int c = 0; c < 4; c++) o[nt][c] = 0.f;
    float m0 = -1e30f, m1 = -1e30f, l0 = 0.f, l1 = 0.f;

    for (int t0 = 0; t0 < NT; t0 += 64) {
        __syncthreads();   // prev compute done before restaging (covers Q on iter 0)
        // K/V: 64 rows x 16 float4 = 1024 float4 -> 4 iters of 256 threads.
#pragma unroll
        for (int i = 0; i < 4; i++) {
            int idx = i * 256 + tid;
            int row = idx >> 4, f4 = idx & 15;
            {
                float4 x = *(const float4*)(kb + (size_t)row * NT + t0 + f4 * 4);
                float4 h = make_float4(tf32r(x.x), tf32r(x.y), tf32r(x.z), tf32r(x.w));
                float4 l = make_float4(tf32r(x.x - h.x), tf32r(x.y - h.y),
                                       tf32r(x.z - h.z), tf32r(x.w - h.w));
                *(float4*)&Kh[row][f4 * 4] = h;
                *(float4*)&Kl[row][f4 * 4] = l;
            }
            {
                float4 x = *(const float4*)(vb + (size_t)(t0 + row) * NHD + f4 * 4);
                *(float4*)&Vh[row][f4 * 4] =
                    make_float4(tf32r(x.x), tf32r(x.y), tf32r(x.z), tf32r(x.w));
            }
        }
        __syncthreads();

        // ---- S = Q K^T : 8 n-tiles x 8 k-tiles, 3 compensation chains ----
        float s[8][4];
#pragma unroll
        for (int nt = 0; nt < 8; nt++)
#pragma unroll
            for (int c = 0; c < 4; c++) s[nt][c] = 0.f;

#pragma unroll
        for (int kt = 0; kt < 8; kt++) {
            float ah[4], al[4];
            ah[0] = Qh[wr + r][kt * 8 + g];         al[0] = Ql[wr + r][kt * 8 + g];
            ah[1] = Qh[wr + r + 8][kt * 8 + g];     al[1] = Ql[wr + r + 8][kt * 8 + g];
            ah[2] = Qh[wr + r][kt * 8 + g + 4];     al[2] = Ql[wr + r][kt * 8 + g + 4];
            ah[3] = Qh[wr + r + 8][kt * 8 + g + 4]; al[3] = Ql[wr + r + 8][kt * 8 + g + 4];
            float bhf[8][2], blf[8][2];
#pragma unroll
            for (int nt = 0; nt < 8; nt++) {
                bhf[nt][0] = Kh[kt * 8 + g][nt * 8 + r];
                bhf[nt][1] = Kh[kt * 8 + g + 4][nt * 8 + r];
                blf[nt][0] = Kl[kt * 8 + g][nt * 8 + r];
                blf[nt][1] = Kl[kt * 8 + g + 4][nt * 8 + r];
            }
#pragma unroll
            for (int nt = 0; nt < 8; nt++) mma_f(s[nt], ah, bhf[nt][0], bhf[nt][1]);
#pragma unroll
            for (int nt = 0; nt < 8; nt++) mma_f(s[nt], ah, blf[nt][0], blf[nt][1]);
#pragma unroll
            for (int nt = 0; nt < 8; nt++) mma_f(s[nt], al, bhf[nt][0], bhf[nt][1]);
        }

        // ---- online softmax (rows r, r+8; quad-wide reductions) ----
        float mx0 = -1e30f, mx1 = -1e30f;
#pragma unroll
        for (int nt = 0; nt < 8; nt++) {
            s[nt][0] *= 0.125f; s[nt][1] *= 0.125f;
            s[nt][2] *= 0.125f; s[nt][3] *= 0.125f;
            mx0 = fmaxf(mx0, fmaxf(s[nt][0], s[nt][1]));
            mx1 = fmaxf(mx1, fmaxf(s[nt][2], s[nt][3]));
        }
        mx0 = fmaxf(mx0, __shfl_xor_sync(0xffffffffu, mx0, 1));
        mx0 = fmaxf(mx0, __shfl_xor_sync(0xffffffffu, mx0, 2));
        mx1 = fmaxf(mx1, __shfl_xor_sync(0xffffffffu, mx1, 1));
        mx1 = fmaxf(mx1, __shfl_xor_sync(0xffffffffu, mx1, 2));

        float mn0 = fmaxf(m0, mx0), mn1 = fmaxf(m1, mx1);
        float c0 = __expf(m0 - mn0), c1 = __expf(m1 - mn1);
        m0 = mn0; m1 = mn1;

        float rs0 = 0.f, rs1 = 0.f;
#pragma unroll
        for (int nt = 0; nt < 8; nt++) {
            float p;
            p = tf32r(__expf(s[nt][0] - mn0)); s[nt][0] = p; rs0 += p;
            p = tf32r(__expf(s[nt][1] - mn0)); s[nt][1] = p; rs0 += p;
            p = tf32r(__expf(s[nt][2] - mn1)); s[nt][2] = p; rs1 += p;
            p = tf32r(__expf(s[nt][3] - mn1)); s[nt][3] = p; rs1 += p;
        }
        rs0 += __shfl_xor_sync(0xffffffffu, rs0, 1);
        rs0 += __shfl_xor_sync(0xffffffffu, rs0, 2);
        rs1 += __shfl_xor_sync(0xffffffffu, rs1, 1);
        rs1 += __shfl_xor_sync(0xffffffffu, rs1, 2);
        l0 = l0 * c0 + rs0;
        l1 = l1 * c1 + rs1;
#pragma unroll
        for (int nt = 0; nt < 8; nt++) {
            o[nt][0] *= c0; o[nt][1] *= c0;
            o[nt][2] *= c1; o[nt][3] *= c1;
        }

        // ---- O += P V : P C-frag -> A-frag via quad shuffles; single V chain ----
        const int src1 = (lane & ~3) | (g >> 1);
        const int src2 = src1 + 2;
        const bool odd = (g & 1) != 0;
#pragma unroll
        for (int kt = 0; kt < 8; kt++) {
            float x0 = __shfl_sync(0xffffffffu, s[kt][0], src1);
            float x1 = __shfl_sync(0xffffffffu, s[kt][1], src1);
            float y0 = __shfl_sync(0xffffffffu, s[kt][2], src1);
            float y1 = __shfl_sync(0xffffffffu, s[kt][3], src1);
            float z0 = __shfl_sync(0xffffffffu, s[kt][0], src2);
            float z1 = __shfl_sync(0xffffffffu, s[kt][1], src2);
            float w0 = __shfl_sync(0xffffffffu, s[kt][2], src2);
            float w1 = __shfl_sync(0xffffffffu, s[kt][3], src2);
            float a[4];
            a[0] = odd ? x1 : x0;
            a[1] = odd ? y1 : y0;
            a[2] = odd ? z1 : z0;
            a[3] = odd ? w1 : w0;

            float vv[8][2];
#pragma unroll
            for (int nt = 0; nt < 8; nt++) {
                vv[nt][0] = Vh[kt * 8 + g][nt * 8 + r];
                vv[nt][1] = Vh[kt * 8 + g + 4][nt * 8 + r];
            }
#pragma unroll
            for (int nt = 0; nt < 8; nt++) mma_f(o[nt], a, vv[nt][0], vv[nt][1]);
        }
    }

    // ---- normalize + store [B,H,T,HD] ----
    float inv0 = 1.f / l0, inv1 = 1.f / l1;
    float* ob = ao + ((size_t)bh * NT + q0 + wr) * NHD;
#pragma unroll
    for (int nt = 0; nt < 8; nt++) {
        int col = nt * 8 + 2 * g;
        *(float2*)(ob + (size_t)r * NHD + col) =
            make_float2(o[nt][0] * inv0, o[nt][1] * inv0);
        *(float2*)(ob + (size_t)(r + 8) * NHD + col) =
            make_float2(o[nt][2] * inv1, o[nt][3] * inv1);
    }
}

// ---------------------------------------------------------------------------
extern "C" void kernel_launch(void* const* d_in, const int* in_sizes, int n_in,
                              void* d_out, int out_size)
{
    const float* q  = (const float*)d_in[0];
    const float* k  = (const float*)d_in[1];
    const float* v  = (const float*)d_in[2];
    const float* Wq = (const float*)d_in[3];
    const float* bq = (const float*)d_in[4];
    const float* Wk = (const float*)d_in[5];
    const float* bk = (const float*)d_in[6];
    const float* Wv = (const float*)d_in[7];
    const float* bv = (const float*)d_in[8];
    const float* Wo = (const float*)d_in[9];
    const float* bo = (const float*)d_in[10];
    float* out = (float*)d_out;

    float *pq, *pkt, *pv, *po;
    cudaGetSymbolAddress((void**)&pq,  g_q);
    cudaGetSymbolAddress((void**)&pkt, g_kt);
    cudaGetSymbolAddress((void**)&pv,  g_v);
    cudaGetSymbolAddress((void**)&po,  g_o);

    const int gemm_smem = 65536;
    cudaFuncSetAttribute(gemm_tc<0,0>, cudaFuncAttributeMaxDynamicSharedMemorySize, gemm_smem);
    cudaFuncSetAttribute(gemm_tc<0,1>, cudaFuncAttributeMaxDynamicSharedMemorySize, gemm_smem);
    cudaFuncSetAttribute(gemm_tc<1,2>, cudaFuncAttributeMaxDynamicSharedMemorySize, gemm_smem);

    dim3 gg(ND / 128, NM / 128);   // (8, 64)

    gemm_tc<0, 0><<<gg, 256, gemm_smem>>>(q, Wq, bq, pq);
    gemm_tc<0, 1><<<gg, 256, gemm_smem>>>(k, Wk, bk, pkt);   // K proj + transpose fused
    gemm_tc<0, 0><<<gg, 256, gemm_smem>>>(v, Wv, bv, pv);

    // smem: Qh+Ql (2*128*72) + Kh+Kl (2*64*72) + Vh (64*72) floats = 129,024 B
    const int attn_smem = (2 * 128 + 2 * 64 + 64) * 72 * (int)sizeof(float);
    cudaFuncSetAttribute(attn_mma, cudaFuncAttributeMaxDynamicSharedMemorySize, attn_smem);
    attn_mma<<<dim3(NT / 128, NB * NH), 256, attn_smem>>>(pq, pkt, pv, po);

    gemm_tc<1, 2><<<gg, 256, gemm_smem>>>(po, Wo, bo, out);
}

// round 8
// speedup vs baseline: 2.0326x; 1.0306x over previous
#include <cuda_runtime.h>
#include <cstdint>

#define NB 4
#define NT 2048
#define ND 1024
#define NH 16
#define NHD 64
#define NM (NB*NT)   // 8192 rows

// Scratch (allocation-free rule: __device__ globals).
__device__ float g_q [NB*NH*NT*NHD];   // [B,H,T,HD]
__device__ float g_kt[NB*NH*NHD*NT];   // [B,H,HD,T]  (K projected + transposed)
__device__ float g_v [NB*NH*NT*NHD];   // [B,H,T,HD]
__device__ float g_o [NB*NH*NT*NHD];   // [B,H,T,HD] attention output

__device__ __forceinline__ unsigned f2tf(float f) {
    unsigned u;
    asm("cvt.rna.tf32.f32 %0, %1;" : "=r"(u) : "f"(f));
    return u;
}
__device__ __forceinline__ float tf32r(float f) { return __uint_as_float(f2tf(f)); }

__device__ __forceinline__ void mma_tf32(float c[4], const unsigned a[4], const unsigned b[2]) {
    asm volatile(
        "mma.sync.aligned.m16n8k8.row.col.f32.tf32.tf32.f32 "
        "{%0,%1,%2,%3}, {%4,%5,%6,%7}, {%8,%9}, {%0,%1,%2,%3};"
        : "+f"(c[0]), "+f"(c[1]), "+f"(c[2]), "+f"(c[3])
        : "r"(a[0]), "r"(a[1]), "r"(a[2]), "r"(a[3]), "r"(b[0]), "r"(b[1]));
}
__device__ __forceinline__ void mma_f(float c[4], const float a[4], const float b0, const float b1) {
    asm volatile(
        "mma.sync.aligned.m16n8k8.row.col.f32.tf32.tf32.f32 "
        "{%0,%1,%2,%3}, {%4,%5,%6,%7}, {%8,%9}, {%0,%1,%2,%3};"
        : "+f"(c[0]), "+f"(c[1]), "+f"(c[2]), "+f"(c[3])
        : "r"(__float_as_uint(a[0])), "r"(__float_as_uint(a[1])),
          "r"(__float_as_uint(a[2])), "r"(__float_as_uint(a[3])),
          "r"(__float_as_uint(b0)),   "r"(__float_as_uint(b1)));
}

// ---------------------------------------------------------------------------
// Tensor-core tf32 GEMM (verbatim from passing R3/R5/R6/R7): C = A@W^T + bias.
// ---------------------------------------------------------------------------
template<int AMODE, int OMODE>
__global__ __launch_bounds__(256)
void gemm_tc(const float* __restrict__ A, const float* __restrict__ W,
             const float* __restrict__ bias, float* __restrict__ Cout)
{
    extern __shared__ unsigned sh[];
    unsigned* As = sh;           // 2 bufs x 4096 u32
    unsigned* Ws = sh + 8192;

    const int tid  = threadIdx.x;
    const int lane = tid & 31;
    const int warp = tid >> 5;
    const int wm   = warp & 1;
    const int wn   = warp >> 1;
    const int bm   = blockIdx.y * 128;
    const int bn   = blockIdx.x * 128;

    float acc[4][4][4];
#pragma unroll
    for (int mi = 0; mi < 4; mi++)
#pragma unroll
        for (int nj = 0; nj < 4; nj++)
#pragma unroll
            for (int r = 0; r < 4; r++) acc[mi][nj][r] = 0.f;

    float4 ar[4], wr[4];

    auto ldg = [&](int s) {
#pragma unroll
        for (int l = 0; l < 4; l++) {
            int idx = l * 256 + tid;
            int row = idx >> 3;
            int kq  = idx & 7;
            int kg  = s * 32 + kq * 4;
            if (AMODE == 0) {
                ar[l] = *(const float4*)(A + (size_t)(bm + row) * ND + kg);
            } else {
                int m  = bm + row;
                int b_ = m >> 11, t_ = m & (NT - 1);
                int h_ = kg >> 6, hd = kg & 63;
                ar[l] = *(const float4*)(A + (((size_t)(b_ * NH + h_) * NT + t_) * NHD + hd));
            }
            wr[l] = *(const float4*)(W + (size_t)(bn + row) * ND + kg);
        }
    };

    auto sts = [&](int buf) {
        unsigned* ab = As + buf * 4096;
        unsigned* wb = Ws + buf * 4096;
#pragma unroll
        for (int l = 0; l < 4; l++) {
            int idx = l * 256 + tid;
            int row = idx >> 3;
            int kq  = idx & 7;
            {
                unsigned* p = ab + (((row >> 4) * 4 + (kq >> 1)) << 7);
                int reg = ((kq & 1) << 1) + ((row >> 3) & 1);
                int lb  = (row & 7) * 4;
                p[(lb + 0) * 4 + reg] = f2tf(ar[l].x);
                p[(lb + 1) * 4 + reg] = f2tf(ar[l].y);
                p[(lb + 2) * 4 + reg] = f2tf(ar[l].z);
                p[(lb + 3) * 4 + reg] = f2tf(ar[l].w);
            }
            {
                unsigned* p = wb + (((row >> 3) * 4 + (kq >> 1)) << 6);
                int reg = (kq & 1);
                int lb  = (row & 7) * 4;
                p[(lb + 0) * 2 + reg] = f2tf(wr[l].x);
                p[(lb + 1) * 2 + reg] = f2tf(wr[l].y);
                p[(lb + 2) * 2 + reg] = f2tf(wr[l].z);
                p[(lb + 3) * 2 + reg] = f2tf(wr[l].w);
            }
        }
    };

    auto compute = [&](int buf) {
        const unsigned* ab = As + buf * 4096;
        const unsigned* wb = Ws + buf * 4096;
#pragma unroll
        for (int kt = 0; kt < 4; kt++) {
            unsigned af[4][4];
#pragma unroll
            for (int mi = 0; mi < 4; mi++) {
                uint4 t = *(const uint4*)(ab + ((((wm * 4 + mi) * 4 + kt)) << 7) + (lane << 2));
                af[mi][0] = t.x; af[mi][1] = t.y; af[mi][2] = t.z; af[mi][3] = t.w;
            }
            unsigned bf[4][2];
#pragma unroll
            for (int nj = 0; nj < 4; nj++) {
                uint2 t = *(const uint2*)(wb + ((((wn * 4 + nj) * 4 + kt)) << 6) + (lane << 1));
                bf[nj][0] = t.x; bf[nj][1] = t.y;
            }
#pragma unroll
            for (int mi = 0; mi < 4; mi++)
#pragma unroll
                for (int nj = 0; nj < 4; nj++)
                    mma_tf32(acc[mi][nj], af[mi], bf[nj]);
        }
    };

    ldg(0);
    sts(0);
    __syncthreads();
    for (int s = 0; s < 32; s++) {
        int buf = s & 1;
        if (s < 31) ldg(s + 1);
        compute(buf);
        if (s < 31) sts(buf ^ 1);
        __syncthreads();
    }

#pragma unroll
    for (int nj = 0; nj < 4; nj++) {
        int col = bn + (wn * 4 + nj) * 8 + (lane & 3) * 2;
        float b0 = bias[col], b1 = bias[col + 1];
#pragma unroll
        for (int mi = 0; mi < 4; mi++) {
            int row = bm + (wm * 4 + mi) * 16 + (lane >> 2);
            float v00 = acc[mi][nj][0] + b0, v01 = acc[mi][nj][1] + b1;
            float v10 = acc[mi][nj][2] + b0, v11 = acc[mi][nj][3] + b1;
            if (OMODE == 2) {
                *(float2*)(Cout + (size_t)row * ND + col)       = make_float2(v00, v01);
                *(float2*)(Cout + (size_t)(row + 8) * ND + col) = make_float2(v10, v11);
            } else if (OMODE == 0) {
                int b_ = row >> 11, t_ = row & (NT - 1);
                int h_ = col >> 6, hd = col & 63;
                float* p = Cout + (((size_t)(b_ * NH + h_) * NT + t_) * NHD + hd);
                *(float2*)p             = make_float2(v00, v01);
                *(float2*)(p + 8 * NHD) = make_float2(v10, v11);
            } else { // OMODE 1: [B,H,HD,T]
                int b_ = row >> 11, t_ = row & (NT - 1);
                int h_ = col >> 6, hd = col & 63;
                float* p = Cout + (((size_t)(b_ * NH + h_) * NHD + hd) * NT + t_);
                p[0]      = v00;
                p[NT]     = v01;
                p[8]      = v10;
                p[NT + 8] = v11;
            }
        }
    }
}

// ---------------------------------------------------------------------------
// Flash attention v4: fragment-order smem staging.
// 256 threads = 8 warps; CTA = 128 queries; warp owns 16 rows (mt = warp).
// smem (u32): QH[0,8192) QL[8192,16384) K[16384,24576) V[24576,28672)
//  - Q A-frag tile (mt*8+kt)*128: uint4 @ lane*4 (regs 0..3)
//  - K B-frag tile (nt*8+kt)*128: uint4 @ lane*4 = [hi0,hi1,lo0,lo1]
//  - V B-frag tile (nt*8+kt)*64 : uint2 @ lane*2 = [reg0,reg1]
// 112 KB total -> 2 CTAs/SM (16 warps). Math bit-identical to R7.
// ---------------------------------------------------------------------------
__global__ __launch_bounds__(256, 2)
void attn_mma(const float* __restrict__ qp, const float* __restrict__ ktp,
              const float* __restrict__ vp, float* __restrict__ ao)
{
    extern __shared__ unsigned smu[];

    const int tid  = threadIdx.x;
    const int lane = tid & 31;
    const int warp = tid >> 5;
    const int r    = lane >> 2;          // 0..7
    const int g    = lane & 3;           // 0..3
    const int bh   = blockIdx.y;
    const int q0   = blockIdx.x * 128;

    const float* qb = qp  + ((size_t)bh * NT + q0) * NHD;
    const float* kb = ktp + (size_t)bh * NHD * NT;
    const float* vb = vp  + (size_t)bh * NT * NHD;

    // ---- Stage Q once in A-frag order (hi/lo). 2048 float4, 8 iters. ----
#pragma unroll
    for (int i = 0; i < 8; i++) {
        int idx = i * 256 + tid;
        int uu = idx & 31, blk = idx >> 5;          // warp spans 8 rows x 4 f4
        int qrow = (uu >> 2) + (blk & 15) * 8;      // 0..127
        int f4   = (uu & 3) + (blk >> 4) * 4;       // 0..15
        float4 x = *(const float4*)(qb + qrow * NHD + f4 * 4);
        float xe[4] = {x.x, x.y, x.z, x.w};
        int mt = qrow >> 4;
        int lb = (qrow & 7) * 4;
        int rr = (qrow >> 3) & 1;
#pragma unroll
        for (int e = 0; e < 4; e++) {
            int hd = f4 * 4 + e;
            int ad = ((mt * 8 + (hd >> 3)) * 128) + (lb + (hd & 3)) * 4
                     + ((hd >> 2) & 1) * 2 + rr;
            float h = tf32r(xe[e]);
            smu[ad]        = __float_as_uint(h);
            smu[8192 + ad] = f2tf(xe[e] - h);
        }
    }

    float o[8][4];
#pragma unroll
    for (int nt = 0; nt < 8; nt++)
#pragma unroll
        for (int c = 0; c < 4; c++) o[nt][c] = 0.f;
    float m0 = -1e30f, m1 = -1e30f, l0 = 0.f, l1 = 0.f;

    for (int t0 = 0; t0 < NT; t0 += 64) {
        __syncthreads();   // prev compute done before restaging (covers Q on iter 0)
        // ---- Stage K (hi/lo interleaved) and V in B-frag order. ----
#pragma unroll
        for (int i = 0; i < 4; i++) {
            int idx = i * 256 + tid;
            int uu = idx & 31, blk = idx >> 5;      // 0..31
            int row = (uu >> 2) + (blk & 7) * 8;    // 0..63
            int f4  = (uu & 3) + (blk >> 3) * 4;    // 0..15
            {   // K: row = hd, f4 indexes keys
                float4 x = *(const float4*)(kb + (size_t)row * NT + t0 + f4 * 4);
                float xe[4] = {x.x, x.y, x.z, x.w};
                int kt = row >> 3;
                int reg = (row >> 2) & 1;
                int lh = row & 3;
#pragma unroll
                for (int e = 0; e < 4; e++) {
                    int key = f4 * 4 + e;
                    int ad = 16384 + (((key >> 3) * 8 + kt) * 128)
                             + ((key & 7) * 4 + lh) * 4 + reg;
                    float h = tf32r(xe[e]);
                    smu[ad]     = __float_as_uint(h);
                    smu[ad + 2] = f2tf(xe[e] - h);
                }
            }
            {   // V: row = key, f4 indexes hd
                float4 y = *(const float4*)(vb + (size_t)(t0 + row) * NHD + f4 * 4);
                float ye[4] = {y.x, y.y, y.z, y.w};
                int kt = row >> 3;
                int reg = (row >> 2) & 1;
                int lk = row & 3;
#pragma unroll
                for (int e = 0; e < 4; e++) {
                    int hd = f4 * 4 + e;
                    int ad = 24576 + (((hd >> 3) * 8 + kt) * 64)
                             + ((hd & 7) * 4 + lk) * 2 + reg;
                    smu[ad] = f2tf(ye[e]);
                }
            }
        }
        __syncthreads();

        // ---- S = Q K^T : frag loads are single LDS.128 ----
        float s[8][4];
#pragma unroll
        for (int nt = 0; nt < 8; nt++)
#pragma unroll
            for (int c = 0; c < 4; c++) s[nt][c] = 0.f;

#pragma unroll
        for (int kt = 0; kt < 8; kt++) {
            uint4 qh4 = *(const uint4*)(smu + (warp * 8 + kt) * 128 + lane * 4);
            uint4 ql4 = *(const uint4*)(smu + 8192 + (warp * 8 + kt) * 128 + lane * 4);
            float ah[4] = {__uint_as_float(qh4.x), __uint_as_float(qh4.y),
                           __uint_as_float(qh4.z), __uint_as_float(qh4.w)};
            float al[4] = {__uint_as_float(ql4.x), __uint_as_float(ql4.y),
                           __uint_as_float(ql4.z), __uint_as_float(ql4.w)};
#pragma unroll
            for (int half = 0; half < 2; half++) {
                uint4 kk[4];
#pragma unroll
                for (int j = 0; j < 4; j++)
                    kk[j] = *(const uint4*)(smu + 16384
                              + (((half * 4 + j) * 8 + kt) * 128) + lane * 4);
#pragma unroll
                for (int j = 0; j < 4; j++)
                    mma_f(s[half*4+j], ah, __uint_as_float(kk[j].x), __uint_as_float(kk[j].y));
#pragma unroll
                for (int j = 0; j < 4; j++)
                    mma_f(s[half*4+j], ah, __uint_as_float(kk[j].z), __uint_as_float(kk[j].w));
#pragma unroll
                for (int j = 0; j < 4; j++)
                    mma_f(s[half*4+j], al, __uint_as_float(kk[j].x), __uint_as_float(kk[j].y));
            }
        }

        // ---- online softmax (rows r, r+8; quad-wide reductions) ----
        float mx0 = -1e30f, mx1 = -1e30f;
#pragma unroll
        for (int nt = 0; nt < 8; nt++) {
            s[nt][0] *= 0.125f; s[nt][1] *= 0.125f;
            s[nt][2] *= 0.125f; s[nt][3] *= 0.125f;
            mx0 = fmaxf(mx0, fmaxf(s[nt][0], s[nt][1]));
            mx1 = fmaxf(mx1, fmaxf(s[nt][2], s[nt][3]));
        }
        mx0 = fmaxf(mx0, __shfl_xor_sync(0xffffffffu, mx0, 1));
        mx0 = fmaxf(mx0, __shfl_xor_sync(0xffffffffu, mx0, 2));
        mx1 = fmaxf(mx1, __shfl_xor_sync(0xffffffffu, mx1, 1));
        mx1 = fmaxf(mx1, __shfl_xor_sync(0xffffffffu, mx1, 2));

        float mn0 = fmaxf(m0, mx0), mn1 = fmaxf(m1, mx1);
        float c0 = __expf(m0 - mn0), c1 = __expf(m1 - mn1);
        m0 = mn0; m1 = mn1;

        float rs0 = 0.f, rs1 = 0.f;
#pragma unroll
        for (int nt = 0; nt < 8; nt++) {
            float p;
            p = tf32r(__expf(s[nt][0] - mn0)); s[nt][0] = p; rs0 += p;
            p = tf32r(__expf(s[nt][1] - mn0)); s[nt][1] = p; rs0 += p;
            p = tf32r(__expf(s[nt][2] - mn1)); s[nt][2] = p; rs1 += p;
            p = tf32r(__expf(s[nt][3] - mn1)); s[nt][3] = p; rs1 += p;
        }
        rs0 += __shfl_xor_sync(0xffffffffu, rs0, 1);
        rs0 += __shfl_xor_sync(0xffffffffu, rs0, 2);
        rs1 += __shfl_xor_sync(0xffffffffu, rs1, 1);
        rs1 += __shfl_xor_sync(0xffffffffu, rs1, 2);
        l0 = l0 * c0 + rs0;
        l1 = l1 * c1 + rs1;
#pragma unroll
        for (int nt = 0; nt < 8; nt++) {
            o[nt][0] *= c0; o[nt][1] *= c0;
            o[nt][2] *= c1; o[nt][3] *= c1;
        }

        // ---- O += P V : P C-frag -> A-frag via quad shuffles; LDS.64 V frags ----
        const int src1 = (lane & ~3) | (g >> 1);
        const int src2 = src1 + 2;
        const bool odd = (g & 1) != 0;
#pragma unroll
        for (int kt = 0; kt < 8; kt++) {
            float x0 = __shfl_sync(0xffffffffu, s[kt][0], src1);
            float x1 = __shfl_sync(0xffffffffu, s[kt][1], src1);
            float y0 = __shfl_sync(0xffffffffu, s[kt][2], src1);
            float y1 = __shfl_sync(0xffffffffu, s[kt][3], src1);
            float z0 = __shfl_sync(0xffffffffu, s[kt][0], src2);
            float z1 = __shfl_sync(0xffffffffu, s[kt][1], src2);
            float w0 = __shfl_sync(0xffffffffu, s[kt][2], src2);
            float w1 = __shfl_sync(0xffffffffu, s[kt][3], src2);
            float a[4];
            a[0] = odd ? x1 : x0;
            a[1] = odd ? y1 : y0;
            a[2] = odd ? z1 : z0;
            a[3] = odd ? w1 : w0;

#pragma unroll
            for (int nt = 0; nt < 8; nt++) {
                uint2 vv = *(const uint2*)(smu + 24576 + ((nt * 8 + kt) * 64) + lane * 2);
                mma_f(o[nt], a, __uint_as_float(vv.x), __uint_as_float(vv.y));
            }
        }
    }

    // ---- normalize + store [B,H,T,HD] ----
    float inv0 = 1.f / l0, inv1 = 1.f / l1;
    float* ob = ao + ((size_t)bh * NT + q0 + warp * 16) * NHD;
#pragma unroll
    for (int nt = 0; nt < 8; nt++) {
        int col = nt * 8 + 2 * g;
        *(float2*)(ob + (size_t)r * NHD + col) =
            make_float2(o[nt][0] * inv0, o[nt][1] * inv0);
        *(float2*)(ob + (size_t)(r + 8) * NHD + col) =
            make_float2(o[nt][2] * inv1, o[nt][3] * inv1);
    }
}

// ---------------------------------------------------------------------------
extern "C" void kernel_launch(void* const* d_in, const int* in_sizes, int n_in,
                              void* d_out, int out_size)
{
    const float* q  = (const float*)d_in[0];
    const float* k  = (const float*)d_in[1];
    const float* v  = (const float*)d_in[2];
    const float* Wq = (const float*)d_in[3];
    const float* bq = (const float*)d_in[4];
    const float* Wk = (const float*)d_in[5];
    const float* bk = (const float*)d_in[6];
    const float* Wv = (const float*)d_in[7];
    const float* bv = (const float*)d_in[8];
    const float* Wo = (const float*)d_in[9];
    const float* bo = (const float*)d_in[10];
    float* out = (float*)d_out;

    float *pq, *pkt, *pv, *po;
    cudaGetSymbolAddress((void**)&pq,  g_q);
    cudaGetSymbolAddress((void**)&pkt, g_kt);
    cudaGetSymbolAddress((void**)&pv,  g_v);
    cudaGetSymbolAddress((void**)&po,  g_o);

    const int gemm_smem = 65536;
    cudaFuncSetAttribute(gemm_tc<0,0>, cudaFuncAttributeMaxDynamicSharedMemorySize, gemm_smem);
    cudaFuncSetAttribute(gemm_tc<0,1>, cudaFuncAttributeMaxDynamicSharedMemorySize, gemm_smem);
    cudaFuncSetAttribute(gemm_tc<1,2>, cudaFuncAttributeMaxDynamicSharedMemorySize, gemm_smem);

    dim3 gg(ND / 128, NM / 128);   // (8, 64)

    gemm_tc<0, 0><<<gg, 256, gemm_smem>>>(q, Wq, bq, pq);
    gemm_tc<0, 1><<<gg, 256, gemm_smem>>>(k, Wk, bk, pkt);   // K proj + transpose fused
    gemm_tc<0, 0><<<gg, 256, gemm_smem>>>(v, Wv, bv, pv);

    const int attn_smem = 28672 * 4;   // 114,688 B -> 2 CTAs/SM
    cudaFuncSetAttribute(attn_mma, cudaFuncAttributeMaxDynamicSharedMemorySize, attn_smem);
    attn_mma<<<dim3(NT / 128, NB * NH), 256, attn_smem>>>(pq, pkt, pv, po);

    gemm_tc<1, 2><<<gg, 256, gemm_smem>>>(po, Wo, bo, out);
}